// round 1
// baseline (speedup 1.0000x reference)
#include <cuda_runtime.h>

// Problem constants
#define Bz    8
#define HHg   32
#define WWg   32
#define Lq    1024          // HHg*WWg
#define Cin   512
#define NHd   4
#define KDim  128
#define Emb   512           // NHd*KDim
#define Mrows 8192          // Bz*Lq

// Scratch (device globals: allocation-free rule)
__device__ float g_Q [Mrows * Emb];
__device__ float g_K [Mrows * Emb];
__device__ float g_V [Mrows * Emb];
__device__ float g_AO[Mrows * Emb];
__device__ float g_RW[Mrows * NHd * 64];   // 63 used, padded to 64
__device__ float g_RH[Mrows * NHd * 64];

// ---------------------------------------------------------------------------
// Tiled fp32 GEMM: C[M,N] = alpha * A[M,K] @ B[K,N]
// 128x128 block tile, K-tile 16, 256 threads, 8x8 per thread.
// Requires M%128==0, N%128==0, K%16==0 (holds for all uses here).
// ---------------------------------------------------------------------------
__global__ __launch_bounds__(256) void gemm128(
    const float* __restrict__ A, const float* __restrict__ Bm,
    float* __restrict__ C, int M, int N, int K, float alpha)
{
    __shared__ float As[16][132];   // [k][m], padded (132*4 bytes, 16B-aligned rows)
    __shared__ float Bs[16][132];   // [k][n]

    const int tid = threadIdx.x;
    const int tx  = tid & 15;       // col group
    const int ty  = tid >> 4;       // row group
    const int m0  = blockIdx.y * 128;
    const int n0  = blockIdx.x * 128;

    float acc[8][8];
#pragma unroll
    for (int i = 0; i < 8; i++)
#pragma unroll
        for (int j = 0; j < 8; j++) acc[i][j] = 0.f;

    const int arow = tid >> 2;          // 0..63
    const int acol = (tid & 3) << 2;    // 0,4,8,12
    const int brow = tid >> 5;          // 0..7
    const int bcol = (tid & 31) << 2;   // 0..124

    const float* Ap0 = A + (m0 + arow) * K + acol;
    const float* Ap1 = A + (m0 + arow + 64) * K + acol;

    for (int k0 = 0; k0 < K; k0 += 16) {
        float4 a0 = *(const float4*)(Ap0 + k0);
        float4 a1 = *(const float4*)(Ap1 + k0);
        float4 b0 = *(const float4*)(Bm + (k0 + brow) * N + n0 + bcol);
        float4 b1 = *(const float4*)(Bm + (k0 + 8 + brow) * N + n0 + bcol);

        As[acol + 0][arow] = a0.x;  As[acol + 1][arow] = a0.y;
        As[acol + 2][arow] = a0.z;  As[acol + 3][arow] = a0.w;
        As[acol + 0][arow + 64] = a1.x;  As[acol + 1][arow + 64] = a1.y;
        As[acol + 2][arow + 64] = a1.z;  As[acol + 3][arow + 64] = a1.w;
        *(float4*)&Bs[brow][bcol]     = b0;
        *(float4*)&Bs[brow + 8][bcol] = b1;
        __syncthreads();

#pragma unroll
        for (int kk = 0; kk < 16; kk++) {
            float4 aA = *(const float4*)&As[kk][ty * 4];
            float4 aB = *(const float4*)&As[kk][ty * 4 + 64];
            float4 bA = *(const float4*)&Bs[kk][tx * 4];
            float4 bB = *(const float4*)&Bs[kk][tx * 4 + 64];
            float av[8] = {aA.x, aA.y, aA.z, aA.w, aB.x, aB.y, aB.z, aB.w};
            float bv[8] = {bA.x, bA.y, bA.z, bA.w, bB.x, bB.y, bB.z, bB.w};
#pragma unroll
            for (int i = 0; i < 8; i++)
#pragma unroll
                for (int j = 0; j < 8; j++)
                    acc[i][j] += av[i] * bv[j];
        }
        __syncthreads();
    }

#pragma unroll
    for (int i = 0; i < 8; i++) {
        int m = m0 + ty * 4 + (i & 3) + ((i >> 2) << 6);
        float4 o0 = make_float4(acc[i][0] * alpha, acc[i][1] * alpha,
                                acc[i][2] * alpha, acc[i][3] * alpha);
        float4 o1 = make_float4(acc[i][4] * alpha, acc[i][5] * alpha,
                                acc[i][6] * alpha, acc[i][7] * alpha);
        *(float4*)(C + m * N + n0 + tx * 4)      = o0;
        *(float4*)(C + m * N + n0 + tx * 4 + 64) = o1;
    }
}

// ---------------------------------------------------------------------------
// Relative position logits: for each (b,i,h):
//   RW[r] = sum_d Q[b,i,h,d] * pos_emb_w[d][r]   (r in 0..62)
//   RH[r] = sum_d Q[b,i,h,d] * pos_emb_h[d][r]
// One block per (b,i) row; 504 active threads cover heads x {W,H} x 63.
// ---------------------------------------------------------------------------
__global__ __launch_bounds__(512) void relpos_kernel(
    const float* __restrict__ Q, const float* __restrict__ pw,
    const float* __restrict__ ph, float* __restrict__ RW,
    float* __restrict__ RH)
{
    __shared__ float qs[Emb];
    const int row = blockIdx.x;  // b*Lq + i
    for (int t = threadIdx.x; t < Emb; t += 512)
        qs[t] = Q[row * Emb + t];
    __syncthreads();

    const int t = threadIdx.x;
    if (t < NHd * 2 * 63) {
        const int h   = t / 126;
        const int rem = t % 126;
        const int tab = rem / 63;
        const int r   = rem % 63;
        const float* pe = tab ? ph : pw;
        const float* q  = &qs[h * KDim];
        float acc = 0.f;
#pragma unroll 8
        for (int d = 0; d < KDim; d++)
            acc += q[d] * pe[d * 63 + r];
        float* outp = tab ? RH : RW;
        outp[(row * NHd + h) * 64 + r] = acc;
    }
}

// ---------------------------------------------------------------------------
// Fused attention with relative position bias + online softmax.
// One block per (query tile of 64, head, batch). 256 threads.
// smem: Qs[128][68] (d-major), Ks[128][68], Vs[64][132], Ss[64][68],
//       RWs[64][64], RHs[64][64], stats.
// ---------------------------------------------------------------------------
#define BM 64
#define BN 64
#define QS_OFF  0
#define KS_OFF  (128 * 68)
#define VS_OFF  (KS_OFF + 128 * 68)
#define SS_OFF  (VS_OFF + 64 * 132)
#define RWS_OFF (SS_OFF + 64 * 68)
#define RHS_OFF (RWS_OFF + 64 * 64)
#define MS_OFF  (RHS_OFF + 64 * 64)
#define LS_OFF  (MS_OFF + 64)
#define FC_OFF  (LS_OFF + 64)
#define ATTN_SMEM_FLOATS (FC_OFF + 64)
#define ATTN_SMEM_BYTES  (ATTN_SMEM_FLOATS * 4)

__global__ __launch_bounds__(256) void attn_kernel(
    const float* __restrict__ Q, const float* __restrict__ Kg,
    const float* __restrict__ Vg, const float* __restrict__ RW,
    const float* __restrict__ RH, float* __restrict__ AO)
{
    extern __shared__ float sm[];
    float* Qs  = sm + QS_OFF;
    float* Ks  = sm + KS_OFF;
    float* Vs  = sm + VS_OFF;
    float* Ss  = sm + SS_OFF;
    float* RWs = sm + RWS_OFF;
    float* RHs = sm + RHS_OFF;
    float* m_s = sm + MS_OFF;
    float* l_s = sm + LS_OFF;
    float* fac = sm + FC_OFF;

    const int tid  = threadIdx.x;
    const int tx   = tid & 15;
    const int ty   = tid >> 4;
    const int m0   = blockIdx.x * BM;
    const int h    = blockIdx.y;
    const int b    = blockIdx.z;
    const int base = (b * Lq) * Emb + h * KDim;  // row 0 of this (b,h), fits int

    // Load Q tile transposed: Qs[d][m]
    for (int idx4 = tid; idx4 < BM * 32; idx4 += 256) {
        int m = idx4 >> 5;
        int d = (idx4 & 31) << 2;
        float4 v = *(const float4*)&Q[base + (m0 + m) * Emb + d];
        Qs[(d + 0) * 68 + m] = v.x;
        Qs[(d + 1) * 68 + m] = v.y;
        Qs[(d + 2) * 68 + m] = v.z;
        Qs[(d + 3) * 68 + m] = v.w;
    }
    // Load relative logit rows for this tile
    const int rbase = ((b * Lq + m0) * NHd + h) * 64;
    for (int idx = tid; idx < 64 * 64; idx += 256) {
        int m = idx >> 6, r = idx & 63;
        RWs[idx] = RW[rbase + m * NHd * 64 + r];
        RHs[idx] = RH[rbase + m * NHd * 64 + r];
    }
    if (tid < 64) { m_s[tid] = -3.0e38f; l_s[tid] = 0.f; }

    float acc[4][8];
#pragma unroll
    for (int i = 0; i < 4; i++)
#pragma unroll
        for (int j = 0; j < 8; j++) acc[i][j] = 0.f;

    __syncthreads();

    for (int n0 = 0; n0 < Lq; n0 += BN) {
        // Load K (transposed) and V (natural) tiles
        for (int idx4 = tid; idx4 < BN * 32; idx4 += 256) {
            int n = idx4 >> 5;
            int d = (idx4 & 31) << 2;
            float4 kv = *(const float4*)&Kg[base + (n0 + n) * Emb + d];
            Ks[(d + 0) * 68 + n] = kv.x;
            Ks[(d + 1) * 68 + n] = kv.y;
            Ks[(d + 2) * 68 + n] = kv.z;
            Ks[(d + 3) * 68 + n] = kv.w;
            float4 vv = *(const float4*)&Vg[base + (n0 + n) * Emb + d];
            *(float4*)&Vs[n * 132 + d] = vv;
        }
        __syncthreads();

        // S = Q K^T + bias  (bias as accumulator init)
        float s[4][4];
#pragma unroll
        for (int i = 0; i < 4; i++) {
            const int m  = ty * 4 + i;
            const int gi = m0 + m;
            const int xm = gi & 31, ym = gi >> 5;
#pragma unroll
            for (int j = 0; j < 4; j++) {
                const int n  = tx * 4 + j;
                const int gj = n0 + n;
                const int xn = gj & 31, yn = gj >> 5;
                s[i][j] = RWs[m * 64 + (xn - xm + 31)] +
                          RHs[m * 64 + (yn - ym + 31)];
            }
        }
#pragma unroll 8
        for (int d = 0; d < KDim; d++) {
            float4 qv = *(const float4*)&Qs[d * 68 + ty * 4];
            float4 kv = *(const float4*)&Ks[d * 68 + tx * 4];
            float qa[4] = {qv.x, qv.y, qv.z, qv.w};
            float ka[4] = {kv.x, kv.y, kv.z, kv.w};
#pragma unroll
            for (int i = 0; i < 4; i++)
#pragma unroll
                for (int j = 0; j < 4; j++)
                    s[i][j] += qa[i] * ka[j];
        }
#pragma unroll
        for (int i = 0; i < 4; i++) {
            *(float4*)&Ss[(ty * 4 + i) * 68 + tx * 4] =
                make_float4(s[i][0], s[i][1], s[i][2], s[i][3]);
        }
        __syncthreads();

        // Online softmax update (warp w owns rows w*8..w*8+7)
        {
            const int warp = tid >> 5, lane = tid & 31;
            for (int rr = 0; rr < 8; rr++) {
                const int row = warp * 8 + rr;
                float s0 = Ss[row * 68 + lane];
                float s1 = Ss[row * 68 + 32 + lane];
                float mx = fmaxf(s0, s1);
#pragma unroll
                for (int o = 16; o; o >>= 1)
                    mx = fmaxf(mx, __shfl_xor_sync(0xffffffffu, mx, o));
                float mold = m_s[row];
                float mnew = fmaxf(mold, mx);
                float p0 = __expf(s0 - mnew);
                float p1 = __expf(s1 - mnew);
                float sum = p0 + p1;
#pragma unroll
                for (int o = 16; o; o >>= 1)
                    sum += __shfl_xor_sync(0xffffffffu, sum, o);
                Ss[row * 68 + lane]      = p0;
                Ss[row * 68 + 32 + lane] = p1;
                if (lane == 0) {
                    float f = __expf(mold - mnew);
                    fac[row] = f;
                    l_s[row] = l_s[row] * f + sum;
                    m_s[row] = mnew;
                }
            }
        }
        __syncthreads();

        // Rescale accumulators, then acc += P @ V
#pragma unroll
        for (int i = 0; i < 4; i++) {
            float f = fac[ty * 4 + i];
#pragma unroll
            for (int j = 0; j < 8; j++) acc[i][j] *= f;
        }
        for (int n = 0; n < BN; n++) {
            float4 v0 = *(const float4*)&Vs[n * 132 + tx * 8];
            float4 v1 = *(const float4*)&Vs[n * 132 + tx * 8 + 4];
            float vb[8] = {v0.x, v0.y, v0.z, v0.w, v1.x, v1.y, v1.z, v1.w};
#pragma unroll
            for (int i = 0; i < 4; i++) {
                float p = Ss[(ty * 4 + i) * 68 + n];
#pragma unroll
                for (int j = 0; j < 8; j++)
                    acc[i][j] += p * vb[j];
            }
        }
        __syncthreads();
    }

    // Normalize and write: AO[b, i, h, d]  (row-major [8192, 512])
#pragma unroll
    for (int i = 0; i < 4; i++) {
        const int m = ty * 4 + i;
        const float inv = 1.0f / l_s[m];
        float4 o0 = make_float4(acc[i][0] * inv, acc[i][1] * inv,
                                acc[i][2] * inv, acc[i][3] * inv);
        float4 o1 = make_float4(acc[i][4] * inv, acc[i][5] * inv,
                                acc[i][6] * inv, acc[i][7] * inv);
        const int off = ((b * Lq + m0 + m) * NHd + h) * KDim + tx * 8;
        *(float4*)&AO[off]     = o0;
        *(float4*)&AO[off + 4] = o1;
    }
}

// ---------------------------------------------------------------------------
extern "C" void kernel_launch(void* const* d_in, const int* in_sizes, int n_in,
                              void* d_out, int out_size)
{
    (void)in_sizes; (void)n_in; (void)out_size;
    const float* x  = (const float*)d_in[0];
    const float* Wq = (const float*)d_in[1];
    const float* Wk = (const float*)d_in[2];
    const float* Wv = (const float*)d_in[3];
    const float* Wo = (const float*)d_in[4];
    const float* pw = (const float*)d_in[5];
    const float* ph = (const float*)d_in[6];
    float* out = (float*)d_out;

    float *q, *k, *v, *ao, *rw, *rh;
    cudaGetSymbolAddress((void**)&q,  g_Q);
    cudaGetSymbolAddress((void**)&k,  g_K);
    cudaGetSymbolAddress((void**)&v,  g_V);
    cudaGetSymbolAddress((void**)&ao, g_AO);
    cudaGetSymbolAddress((void**)&rw, g_RW);
    cudaGetSymbolAddress((void**)&rh, g_RH);

    const float scale = 0.08838834764831845f;  // 1/sqrt(128)

    dim3 gemm_grid(Emb / 128, Mrows / 128);
    gemm128<<<gemm_grid, 256>>>(x, Wq, q, Mrows, Emb, Cin, scale);
    gemm128<<<gemm_grid, 256>>>(x, Wk, k, Mrows, Emb, Cin, 1.0f);
    gemm128<<<gemm_grid, 256>>>(x, Wv, v, Mrows, Emb, Cin, 1.0f);

    relpos_kernel<<<Mrows, 512>>>(q, pw, ph, rw, rh);

    cudaFuncSetAttribute(attn_kernel,
                         cudaFuncAttributeMaxDynamicSharedMemorySize,
                         ATTN_SMEM_BYTES);
    attn_kernel<<<dim3(Lq / BM, NHd, Bz), 256, ATTN_SMEM_BYTES>>>(
        q, k, v, rw, rh, ao);

    gemm128<<<gemm_grid, 256>>>(ao, Wo, out, Mrows, Emb, Emb, 1.0f);
}

// round 4
// speedup vs baseline: 1.2505x; 1.2505x over previous
#include <cuda_runtime.h>
#include <cstdint>

// Problem constants
#define Bz    8
#define HHg   32
#define WWg   32
#define Lq    1024          // HHg*WWg
#define Cin   512
#define NHd   4
#define KDim  128
#define Emb   512           // NHd*KDim
#define Mrows 8192          // Bz*Lq

// Scratch (device globals: allocation-free rule)
__device__ float g_Q  [Mrows * Emb];
__device__ float g_K  [Mrows * Emb];
__device__ float g_V  [Mrows * Emb];
__device__ float g_AO [Mrows * Emb];
__device__ float g_RW [Mrows * NHd * 64];   // 63 used, padded to 64
__device__ float g_RH [Mrows * NHd * 64];
__device__ float g_Wt [3 * Emb * Cin];      // transposed Wq|Wk|Wv, [1536][512]
__device__ float g_WtO[Emb * Emb];          // transposed Wo, [512][512]

// ===========================================================================
// Helpers
// ===========================================================================
__device__ __forceinline__ uint32_t smem_u32(const void* p) {
    uint32_t a;
    asm("{ .reg .u64 t; cvta.to.shared.u64 t, %1; cvt.u32.u64 %0, t; }"
        : "=r"(a) : "l"(p));
    return a;
}
__device__ __forceinline__ uint32_t f2tf(float f) {
    uint32_t r;
    asm("cvt.rna.tf32.f32 %0, %1;" : "=r"(r) : "f"(f));
    return r;
}
#define CP_ASYNC16(dst, src) \
    asm volatile("cp.async.cg.shared.global [%0], [%1], 16;" \
                 :: "r"(dst), "l"(src) : "memory")
#define CP_COMMIT() asm volatile("cp.async.commit_group;" ::: "memory")
#define CP_WAIT1()  asm volatile("cp.async.wait_group 1;" ::: "memory")
#define CP_WAIT0()  asm volatile("cp.async.wait_group 0;" ::: "memory")

__device__ __forceinline__ void mma_tf32(float* c, const uint32_t* a,
                                         const uint32_t* b) {
    asm volatile(
        "mma.sync.aligned.m16n8k8.row.col.f32.tf32.tf32.f32 "
        "{%0,%1,%2,%3}, {%4,%5,%6,%7}, {%8,%9}, {%0,%1,%2,%3};"
        : "+f"(c[0]), "+f"(c[1]), "+f"(c[2]), "+f"(c[3])
        : "r"(a[0]), "r"(a[1]), "r"(a[2]), "r"(a[3]), "r"(b[0]), "r"(b[1]));
}

// ===========================================================================
// Weight transpose: Wt[n][k] = W[k][n] for Wq|Wk|Wv (fused) and Wo.
// ===========================================================================
__global__ __launch_bounds__(256) void transpose_w(
    const float* __restrict__ Wq, const float* __restrict__ Wk,
    const float* __restrict__ Wv, const float* __restrict__ Wo,
    float* __restrict__ Wt, float* __restrict__ WtO)
{
    __shared__ float t[32][33];
    const int z = blockIdx.z;
    const float* W = (z == 0) ? Wq : (z == 1) ? Wk : (z == 2) ? Wv : Wo;
    float* O = (z == 3) ? WtO : (Wt + z * Emb * Cin);
    const int tx = threadIdx.x & 31, ty = threadIdx.x >> 5;  // 32 x 8
    const int k0 = blockIdx.y * 32, n0 = blockIdx.x * 32;
#pragma unroll
    for (int i = 0; i < 4; i++)
        t[ty + i * 8][tx] = W[(k0 + ty + i * 8) * 512 + n0 + tx];
    __syncthreads();
#pragma unroll
    for (int i = 0; i < 4; i++)
        O[(n0 + ty + i * 8) * 512 + k0 + tx] = t[tx][ty + i * 8];
}

// ===========================================================================
// tf32 mma.sync GEMM: C = alpha * A[M,512] @ Bt[N,512]^T
// CTA tile 128x128, 8 warps (warp tile 32x64), K-chunk 32, 2-stage cp.async.
// gridDim.x selects (output, n-tile): outi = bx>>2 -> C0/C1/C2, col=(bx&3)*128,
// Bt row block = bx*128 (Bt may be [1536][512] fused or [512][512]).
// smem per stage per operand: 128 rows x 36 floats = 18432 B.
// ===========================================================================
#define GEMM_STAGE_FLOATS (2 * 128 * 36)          // A+B one stage: 9216 floats
#define GEMM_SMEM_BYTES   (2 * GEMM_STAGE_FLOATS * 4)  // 73728

__global__ __launch_bounds__(256) void gemm_mma(
    const float* __restrict__ A, const float* __restrict__ Bt,
    float* __restrict__ C0, float* __restrict__ C1, float* __restrict__ C2,
    float alpha0)
{
    extern __shared__ float smf[];
    const uint32_t sb = smem_u32(smf);
    const int tid  = threadIdx.x;
    const int lane = tid & 31, wid = tid >> 5;
    const int warp_m = wid & 3, warp_n = wid >> 2;
    const int gid = lane >> 2, tig = lane & 3;     // groupID, threadID_in_group

    const int bx   = blockIdx.x;
    const int outi = bx >> 2;
    float* C = (outi == 0) ? C0 : (outi == 1) ? C1 : C2;
    const float alpha = (outi == 0) ? alpha0 : 1.0f;
    const int m0    = blockIdx.y * 128;
    const int nrow0 = bx * 128;
    const int ncol0 = (bx & 3) * 128;

    const float* Ab = A  + m0 * 512;
    const float* Bb = Bt + nrow0 * 512;

    float c[2][8][4];
#pragma unroll
    for (int mf = 0; mf < 2; mf++)
#pragma unroll
        for (int nf = 0; nf < 8; nf++)
#pragma unroll
            for (int e = 0; e < 4; e++) c[mf][nf][e] = 0.f;

    auto issue = [&](int kc, int s) {
#pragma unroll
        for (int it = 0; it < 4; it++) {
            const int idx4 = it * 256 + tid;   // 0..1023
            const int m  = idx4 >> 3;
            const int k4 = idx4 & 7;
            const uint32_t so = sb + s * (GEMM_STAGE_FLOATS * 4)
                                + m * 144 + k4 * 16;
            CP_ASYNC16(so,         Ab + m * 512 + kc * 32 + k4 * 4);
            CP_ASYNC16(so + 18432, Bb + m * 512 + kc * 32 + k4 * 4);
        }
        CP_COMMIT();
    };

    issue(0, 0);

    for (int kc = 0; kc < 16; kc++) {
        const int s = kc & 1;
        if (kc < 15) { issue(kc + 1, s ^ 1); CP_WAIT1(); }
        else         { CP_WAIT0(); }
        __syncthreads();

        const float* As = smf + s * GEMM_STAGE_FLOATS;
        const float* Bs = As + 128 * 36;

#pragma unroll
        for (int k8 = 0; k8 < 4; k8++) {
            const int kb = k8 * 8 + tig;
            uint32_t a[2][4], b[8][2];
#pragma unroll
            for (int mf = 0; mf < 2; mf++) {
                const int r0 = warp_m * 32 + mf * 16 + gid;
                a[mf][0] = f2tf(As[r0 * 36 + kb]);
                a[mf][1] = f2tf(As[(r0 + 8) * 36 + kb]);
                a[mf][2] = f2tf(As[r0 * 36 + kb + 4]);
                a[mf][3] = f2tf(As[(r0 + 8) * 36 + kb + 4]);
            }
#pragma unroll
            for (int nf = 0; nf < 8; nf++) {
                const int n = warp_n * 64 + nf * 8 + gid;
                b[nf][0] = f2tf(Bs[n * 36 + kb]);
                b[nf][1] = f2tf(Bs[n * 36 + kb + 4]);
            }
#pragma unroll
            for (int mf = 0; mf < 2; mf++)
#pragma unroll
                for (int nf = 0; nf < 8; nf++)
                    mma_tf32(c[mf][nf], a[mf], b[nf]);
        }
        __syncthreads();
    }

    // Epilogue
#pragma unroll
    for (int mf = 0; mf < 2; mf++) {
        const int row = m0 + warp_m * 32 + mf * 16 + gid;
#pragma unroll
        for (int nf = 0; nf < 8; nf++) {
            const int col = ncol0 + warp_n * 64 + nf * 8 + tig * 2;
            float2 lo = make_float2(c[mf][nf][0] * alpha, c[mf][nf][1] * alpha);
            float2 hi = make_float2(c[mf][nf][2] * alpha, c[mf][nf][3] * alpha);
            *(float2*)(C + row * 512 + col)       = lo;
            *(float2*)(C + (row + 8) * 512 + col) = hi;
        }
    }
}

// ===========================================================================
// relpos as a register-blocked GEMM: [32768,128] @ concat(pw,ph)[128,126]
// block: 128 rows, pos tables resident in smem (loaded once per block).
// ===========================================================================
#define RP_STRIDE 132
#define RP_SMEM_FLOATS (2 * 128 * RP_STRIDE)
#define RP_SMEM_BYTES  (RP_SMEM_FLOATS * 4)

__global__ __launch_bounds__(256) void relpos_gemm(
    const float* __restrict__ Q, const float* __restrict__ pw,
    const float* __restrict__ ph, float* __restrict__ RW,
    float* __restrict__ RH)
{
    extern __shared__ float sm[];
    float* As = sm;                       // [k][m] 128x132
    float* Ps = sm + 128 * RP_STRIDE;     // [k][c] 128x132 (c: 0-62 W, 64-126 H)

    const int tid = threadIdx.x;
    const int tx  = tid & 15, ty = tid >> 4;
    const int rowbase = blockIdx.x * 128;   // into flat [32768][128]

    for (int it = 0; it < 16; it++) {
        const int idx = it * 256 + tid;     // 4096 float4
        const int m = idx >> 5, k4 = idx & 31;
        float4 v = *(const float4*)(Q + (rowbase + m) * 128 + k4 * 4);
        As[(k4 * 4 + 0) * RP_STRIDE + m] = v.x;
        As[(k4 * 4 + 1) * RP_STRIDE + m] = v.y;
        As[(k4 * 4 + 2) * RP_STRIDE + m] = v.z;
        As[(k4 * 4 + 3) * RP_STRIDE + m] = v.w;
    }
    for (int idx = tid; idx < 128 * 128; idx += 256) {
        const int k = idx >> 7, c = idx & 127;
        float v = 0.f;
        if (c < 63)                  v = pw[k * 63 + c];
        else if (c >= 64 && c < 127) v = ph[k * 63 + (c - 64)];
        Ps[k * RP_STRIDE + c] = v;
    }
    __syncthreads();

    float acc[8][8];
#pragma unroll
    for (int i = 0; i < 8; i++)
#pragma unroll
        for (int j = 0; j < 8; j++) acc[i][j] = 0.f;

#pragma unroll 4
    for (int k = 0; k < 128; k++) {
        float4 a0 = *(const float4*)&As[k * RP_STRIDE + ty * 4];
        float4 a1 = *(const float4*)&As[k * RP_STRIDE + ty * 4 + 64];
        float4 b0 = *(const float4*)&Ps[k * RP_STRIDE + tx * 4];
        float4 b1 = *(const float4*)&Ps[k * RP_STRIDE + tx * 4 + 64];
        float av[8] = {a0.x, a0.y, a0.z, a0.w, a1.x, a1.y, a1.z, a1.w};
        float bv[8] = {b0.x, b0.y, b0.z, b0.w, b1.x, b1.y, b1.z, b1.w};
#pragma unroll
        for (int i = 0; i < 8; i++)
#pragma unroll
            for (int j = 0; j < 8; j++)
                acc[i][j] += av[i] * bv[j];
    }

#pragma unroll
    for (int i = 0; i < 8; i++) {
        const int m = ty * 4 + (i & 3) + ((i >> 2) << 6);
        const int row = rowbase + m;
#pragma unroll
        for (int j = 0; j < 8; j++) {
            const int cc = tx * 4 + (j & 3) + ((j >> 2) << 6);
            if (cc < 63)                   RW[row * 64 + cc]        = acc[i][j];
            else if (cc >= 64 && cc < 127) RH[row * 64 + (cc - 64)] = acc[i][j];
        }
    }
}

// ===========================================================================
// Fused attention (verified in R0): online softmax + relative bias.
// ===========================================================================
#define BM 64
#define BN 64
#define QS_OFF  0
#define KS_OFF  (128 * 68)
#define VS_OFF  (KS_OFF + 128 * 68)
#define SS_OFF  (VS_OFF + 64 * 132)
#define RWS_OFF (SS_OFF + 64 * 68)
#define RHS_OFF (RWS_OFF + 64 * 64)
#define MS_OFF  (RHS_OFF + 64 * 64)
#define LS_OFF  (MS_OFF + 64)
#define FC_OFF  (LS_OFF + 64)
#define ATTN_SMEM_FLOATS (FC_OFF + 64)
#define ATTN_SMEM_BYTES  (ATTN_SMEM_FLOATS * 4)

__global__ __launch_bounds__(256) void attn_kernel(
    const float* __restrict__ Q, const float* __restrict__ Kg,
    const float* __restrict__ Vg, const float* __restrict__ RW,
    const float* __restrict__ RH, float* __restrict__ AO)
{
    extern __shared__ float sm[];
    float* Qs  = sm + QS_OFF;
    float* Ks  = sm + KS_OFF;
    float* Vs  = sm + VS_OFF;
    float* Ss  = sm + SS_OFF;
    float* RWs = sm + RWS_OFF;
    float* RHs = sm + RHS_OFF;
    float* m_s = sm + MS_OFF;
    float* l_s = sm + LS_OFF;
    float* fac = sm + FC_OFF;

    const int tid  = threadIdx.x;
    const int tx   = tid & 15;
    const int ty   = tid >> 4;
    const int m0   = blockIdx.x * BM;
    const int h    = blockIdx.y;
    const int b    = blockIdx.z;
    const int base = (b * Lq) * Emb + h * KDim;

    for (int idx4 = tid; idx4 < BM * 32; idx4 += 256) {
        int m = idx4 >> 5;
        int d = (idx4 & 31) << 2;
        float4 v = *(const float4*)&Q[base + (m0 + m) * Emb + d];
        Qs[(d + 0) * 68 + m] = v.x;
        Qs[(d + 1) * 68 + m] = v.y;
        Qs[(d + 2) * 68 + m] = v.z;
        Qs[(d + 3) * 68 + m] = v.w;
    }
    const int rbase = ((b * Lq + m0) * NHd + h) * 64;
    for (int idx = tid; idx < 64 * 64; idx += 256) {
        int m = idx >> 6, r = idx & 63;
        RWs[idx] = RW[rbase + m * NHd * 64 + r];
        RHs[idx] = RH[rbase + m * NHd * 64 + r];
    }
    if (tid < 64) { m_s[tid] = -3.0e38f; l_s[tid] = 0.f; }

    float acc[4][8];
#pragma unroll
    for (int i = 0; i < 4; i++)
#pragma unroll
        for (int j = 0; j < 8; j++) acc[i][j] = 0.f;

    __syncthreads();

    for (int n0 = 0; n0 < Lq; n0 += BN) {
        for (int idx4 = tid; idx4 < BN * 32; idx4 += 256) {
            int n = idx4 >> 5;
            int d = (idx4 & 31) << 2;
            float4 kv = *(const float4*)&Kg[base + (n0 + n) * Emb + d];
            Ks[(d + 0) * 68 + n] = kv.x;
            Ks[(d + 1) * 68 + n] = kv.y;
            Ks[(d + 2) * 68 + n] = kv.z;
            Ks[(d + 3) * 68 + n] = kv.w;
            float4 vv = *(const float4*)&Vg[base + (n0 + n) * Emb + d];
            *(float4*)&Vs[n * 132 + d] = vv;
        }
        __syncthreads();

        float s[4][4];
#pragma unroll
        for (int i = 0; i < 4; i++) {
            const int m  = ty * 4 + i;
            const int gi = m0 + m;
            const int xm = gi & 31, ym = gi >> 5;
#pragma unroll
            for (int j = 0; j < 4; j++) {
                const int n  = tx * 4 + j;
                const int gj = n0 + n;
                const int xn = gj & 31, yn = gj >> 5;
                s[i][j] = RWs[m * 64 + (xn - xm + 31)] +
                          RHs[m * 64 + (yn - ym + 31)];
            }
        }
#pragma unroll 8
        for (int d = 0; d < KDim; d++) {
            float4 qv = *(const float4*)&Qs[d * 68 + ty * 4];
            float4 kv = *(const float4*)&Ks[d * 68 + tx * 4];
            float qa[4] = {qv.x, qv.y, qv.z, qv.w};
            float ka[4] = {kv.x, kv.y, kv.z, kv.w};
#pragma unroll
            for (int i = 0; i < 4; i++)
#pragma unroll
                for (int j = 0; j < 4; j++)
                    s[i][j] += qa[i] * ka[j];
        }
#pragma unroll
        for (int i = 0; i < 4; i++) {
            *(float4*)&Ss[(ty * 4 + i) * 68 + tx * 4] =
                make_float4(s[i][0], s[i][1], s[i][2], s[i][3]);
        }
        __syncthreads();

        {
            const int warp = tid >> 5, lane = tid & 31;
            for (int rr = 0; rr < 8; rr++) {
                const int row = warp * 8 + rr;
                float s0 = Ss[row * 68 + lane];
                float s1 = Ss[row * 68 + 32 + lane];
                float mx = fmaxf(s0, s1);
#pragma unroll
                for (int o = 16; o; o >>= 1)
                    mx = fmaxf(mx, __shfl_xor_sync(0xffffffffu, mx, o));
                float mold = m_s[row];
                float mnew = fmaxf(mold, mx);
                float p0 = __expf(s0 - mnew);
                float p1 = __expf(s1 - mnew);
                float sum = p0 + p1;
#pragma unroll
                for (int o = 16; o; o >>= 1)
                    sum += __shfl_xor_sync(0xffffffffu, sum, o);
                Ss[row * 68 + lane]      = p0;
                Ss[row * 68 + 32 + lane] = p1;
                if (lane == 0) {
                    float f = __expf(mold - mnew);
                    fac[row] = f;
                    l_s[row] = l_s[row] * f + sum;
                    m_s[row] = mnew;
                }
            }
        }
        __syncthreads();

#pragma unroll
        for (int i = 0; i < 4; i++) {
            float f = fac[ty * 4 + i];
#pragma unroll
            for (int j = 0; j < 8; j++) acc[i][j] *= f;
        }
        for (int n = 0; n < BN; n++) {
            float4 v0 = *(const float4*)&Vs[n * 132 + tx * 8];
            float4 v1 = *(const float4*)&Vs[n * 132 + tx * 8 + 4];
            float vb[8] = {v0.x, v0.y, v0.z, v0.w, v1.x, v1.y, v1.z, v1.w};
#pragma unroll
            for (int i = 0; i < 4; i++) {
                float p = Ss[(ty * 4 + i) * 68 + n];
#pragma unroll
                for (int j = 0; j < 8; j++)
                    acc[i][j] += p * vb[j];
            }
        }
        __syncthreads();
    }

#pragma unroll
    for (int i = 0; i < 4; i++) {
        const int m = ty * 4 + i;
        const float inv = 1.0f / l_s[m];
        float4 o0 = make_float4(acc[i][0] * inv, acc[i][1] * inv,
                                acc[i][2] * inv, acc[i][3] * inv);
        float4 o1 = make_float4(acc[i][4] * inv, acc[i][5] * inv,
                                acc[i][6] * inv, acc[i][7] * inv);
        const int off = ((b * Lq + m0 + m) * NHd + h) * KDim + tx * 8;
        *(float4*)&AO[off]     = o0;
        *(float4*)&AO[off + 4] = o1;
    }
}

// ---------------------------------------------------------------------------
extern "C" void kernel_launch(void* const* d_in, const int* in_sizes, int n_in,
                              void* d_out, int out_size)
{
    (void)in_sizes; (void)n_in; (void)out_size;
    const float* x  = (const float*)d_in[0];
    const float* Wq = (const float*)d_in[1];
    const float* Wk = (const float*)d_in[2];
    const float* Wv = (const float*)d_in[3];
    const float* Wo = (const float*)d_in[4];
    const float* pw = (const float*)d_in[5];
    const float* ph = (const float*)d_in[6];
    float* out = (float*)d_out;

    float *q, *k, *v, *ao, *rw, *rh, *wt, *wto;
    cudaGetSymbolAddress((void**)&q,   g_Q);
    cudaGetSymbolAddress((void**)&k,   g_K);
    cudaGetSymbolAddress((void**)&v,   g_V);
    cudaGetSymbolAddress((void**)&ao,  g_AO);
    cudaGetSymbolAddress((void**)&rw,  g_RW);
    cudaGetSymbolAddress((void**)&rh,  g_RH);
    cudaGetSymbolAddress((void**)&wt,  g_Wt);
    cudaGetSymbolAddress((void**)&wto, g_WtO);

    const float scale = 0.08838834764831845f;  // 1/sqrt(128)

    cudaFuncSetAttribute(gemm_mma,
                         cudaFuncAttributeMaxDynamicSharedMemorySize,
                         GEMM_SMEM_BYTES);
    cudaFuncSetAttribute(relpos_gemm,
                         cudaFuncAttributeMaxDynamicSharedMemorySize,
                         RP_SMEM_BYTES);
    cudaFuncSetAttribute(attn_kernel,
                         cudaFuncAttributeMaxDynamicSharedMemorySize,
                         ATTN_SMEM_BYTES);

    // Transpose weights (Wq|Wk|Wv fused -> g_Wt [1536][512], Wo -> g_WtO)
    transpose_w<<<dim3(16, 16, 4), 256>>>(Wq, Wk, Wv, Wo, wt, wto);

    // Fused QKV GEMM: grid.x 0..11 -> (Q|K|V) x 4 col-tiles
    gemm_mma<<<dim3(12, 64), 256, GEMM_SMEM_BYTES>>>(x, wt, q, k, v, scale);

    // Relative position logits
    relpos_gemm<<<256, 256, RP_SMEM_BYTES>>>(q, pw, ph, rw, rh);

    // Attention
    attn_kernel<<<dim3(Lq / BM, NHd, Bz), 256, ATTN_SMEM_BYTES>>>(
        q, k, v, rw, rh, ao);

    // Output projection
    gemm_mma<<<dim3(4, 64), 256, GEMM_SMEM_BYTES>>>(ao, wto, out, out, out, 1.0f);
}

// round 5
// speedup vs baseline: 3.1948x; 2.5549x over previous
#include <cuda_runtime.h>
#include <cstdint>

// Problem constants
#define Bz    8
#define HHg   32
#define WWg   32
#define Lq    1024          // HHg*WWg
#define Cin   512
#define NHd   4
#define KDim  128
#define Emb   512           // NHd*KDim
#define Mrows 8192          // Bz*Lq

// Scratch (device globals: allocation-free rule)
__device__ float g_Q  [Mrows * Emb];
__device__ float g_K  [Mrows * Emb];
__device__ float g_V  [Mrows * Emb];
__device__ float g_Vt [Bz * NHd * KDim * Lq];  // V transposed: [b][h][d][key]
__device__ float g_AO [Mrows * Emb];
__device__ float g_RW [Mrows * NHd * 64];   // 63 used, padded to 64
__device__ float g_RH [Mrows * NHd * 64];
__device__ float g_Wt [3 * Emb * Cin];      // transposed Wq|Wk|Wv, [1536][512]
__device__ float g_WtO[Emb * Emb];          // transposed Wo, [512][512]

// ===========================================================================
// Helpers
// ===========================================================================
__device__ __forceinline__ uint32_t smem_u32(const void* p) {
    uint32_t a;
    asm("{ .reg .u64 t; cvta.to.shared.u64 t, %1; cvt.u32.u64 %0, t; }"
        : "=r"(a) : "l"(p));
    return a;
}
__device__ __forceinline__ uint32_t f2tf(float f) {
    uint32_t r;
    asm("cvt.rna.tf32.f32 %0, %1;" : "=r"(r) : "f"(f));
    return r;
}
#define CP_ASYNC16(dst, src) \
    asm volatile("cp.async.cg.shared.global [%0], [%1], 16;" \
                 :: "r"(dst), "l"(src) : "memory")
#define CP_COMMIT() asm volatile("cp.async.commit_group;" ::: "memory")
#define CP_WAIT1()  asm volatile("cp.async.wait_group 1;" ::: "memory")
#define CP_WAIT0()  asm volatile("cp.async.wait_group 0;" ::: "memory")

__device__ __forceinline__ void mma_tf32(float* c, const uint32_t* a,
                                         const uint32_t* b) {
    asm volatile(
        "mma.sync.aligned.m16n8k8.row.col.f32.tf32.tf32.f32 "
        "{%0,%1,%2,%3}, {%4,%5,%6,%7}, {%8,%9}, {%0,%1,%2,%3};"
        : "+f"(c[0]), "+f"(c[1]), "+f"(c[2]), "+f"(c[3])
        : "r"(a[0]), "r"(a[1]), "r"(a[2]), "r"(a[3]), "r"(b[0]), "r"(b[1]));
}

// Fast exp2 on the FMA pipe (x <= 0, clamped): rint-split + deg-5 Taylor.
__device__ __forceinline__ float fexp2(float x) {
    x = fmaxf(x, -120.f);
    float r = rintf(x);
    float f = x - r;                       // f in [-0.5, 0.5]
    float p =              0.0013333558f;
    p = fmaf(p, f, 0.0096181291f);
    p = fmaf(p, f, 0.0555041087f);
    p = fmaf(p, f, 0.2402265069f);
    p = fmaf(p, f, 0.6931471806f);
    p = fmaf(p, f, 1.0f);
    int e = (int)r;
    return p * __int_as_float((e + 127) << 23);
}
#define L2E 1.4426950408889634f

// ===========================================================================
// Weight transpose: Wt[n][k] = W[k][n] for Wq|Wk|Wv (fused) and Wo.
// ===========================================================================
__global__ __launch_bounds__(256) void transpose_w(
    const float* __restrict__ Wq, const float* __restrict__ Wk,
    const float* __restrict__ Wv, const float* __restrict__ Wo,
    float* __restrict__ Wt, float* __restrict__ WtO)
{
    __shared__ float t[32][33];
    const int z = blockIdx.z;
    const float* W = (z == 0) ? Wq : (z == 1) ? Wk : (z == 2) ? Wv : Wo;
    float* O = (z == 3) ? WtO : (Wt + z * Emb * Cin);
    const int tx = threadIdx.x & 31, ty = threadIdx.x >> 5;  // 32 x 8
    const int k0 = blockIdx.y * 32, n0 = blockIdx.x * 32;
#pragma unroll
    for (int i = 0; i < 4; i++)
        t[ty + i * 8][tx] = W[(k0 + ty + i * 8) * 512 + n0 + tx];
    __syncthreads();
#pragma unroll
    for (int i = 0; i < 4; i++)
        O[(n0 + ty + i * 8) * 512 + k0 + tx] = t[tx][ty + i * 8];
}

// ===========================================================================
// V transpose per (b,h): Vt[b][h][d][key] = V[b*1024+key][h*128+d],
// pre-truncated to tf32.
// ===========================================================================
__global__ __launch_bounds__(256) void vtrans(
    const float* __restrict__ V, float* __restrict__ Vt)
{
    __shared__ float t[32][33];
    const int bh = blockIdx.z;           // b*4 + h
    const int b = bh >> 2, h = bh & 3;
    const int k0 = blockIdx.x * 32, d0 = blockIdx.y * 32;
    const int tx = threadIdx.x & 31, ty = threadIdx.x >> 5;
#pragma unroll
    for (int i = 0; i < 4; i++)
        t[ty + i * 8][tx] = V[(b * Lq + k0 + ty + i * 8) * Emb + h * KDim + d0 + tx];
    __syncthreads();
#pragma unroll
    for (int i = 0; i < 4; i++)
        Vt[(bh * KDim + d0 + ty + i * 8) * Lq + k0 + tx] =
            __uint_as_float(f2tf(t[tx][ty + i * 8]));
}

// ===========================================================================
// tf32 mma.sync GEMM (unchanged from R4, + K output pre-truncated to tf32)
// ===========================================================================
#define GEMM_STAGE_FLOATS (2 * 128 * 36)
#define GEMM_SMEM_BYTES   (2 * GEMM_STAGE_FLOATS * 4)

__global__ __launch_bounds__(256) void gemm_mma(
    const float* __restrict__ A, const float* __restrict__ Bt,
    float* __restrict__ C0, float* __restrict__ C1, float* __restrict__ C2,
    float alpha0)
{
    extern __shared__ float smf[];
    const uint32_t sb = smem_u32(smf);
    const int tid  = threadIdx.x;
    const int lane = tid & 31, wid = tid >> 5;
    const int warp_m = wid & 3, warp_n = wid >> 2;
    const int gid = lane >> 2, tig = lane & 3;

    const int bx   = blockIdx.x;
    const int outi = bx >> 2;
    float* C = (outi == 0) ? C0 : (outi == 1) ? C1 : C2;
    const float alpha = (outi == 0) ? alpha0 : 1.0f;
    const bool trunc = (outi == 1);      // K output: pre-round to tf32
    const int m0    = blockIdx.y * 128;
    const int nrow0 = bx * 128;
    const int ncol0 = (bx & 3) * 128;

    const float* Ab = A  + m0 * 512;
    const float* Bb = Bt + nrow0 * 512;

    float c[2][8][4];
#pragma unroll
    for (int mf = 0; mf < 2; mf++)
#pragma unroll
        for (int nf = 0; nf < 8; nf++)
#pragma unroll
            for (int e = 0; e < 4; e++) c[mf][nf][e] = 0.f;

    auto issue = [&](int kc, int s) {
#pragma unroll
        for (int it = 0; it < 4; it++) {
            const int idx4 = it * 256 + tid;
            const int m  = idx4 >> 3;
            const int k4 = idx4 & 7;
            const uint32_t so = sb + s * (GEMM_STAGE_FLOATS * 4)
                                + m * 144 + k4 * 16;
            CP_ASYNC16(so,         Ab + m * 512 + kc * 32 + k4 * 4);
            CP_ASYNC16(so + 18432, Bb + m * 512 + kc * 32 + k4 * 4);
        }
        CP_COMMIT();
    };

    issue(0, 0);

    for (int kc = 0; kc < 16; kc++) {
        const int s = kc & 1;
        if (kc < 15) { issue(kc + 1, s ^ 1); CP_WAIT1(); }
        else         { CP_WAIT0(); }
        __syncthreads();

        const float* As = smf + s * GEMM_STAGE_FLOATS;
        const float* Bs = As + 128 * 36;

#pragma unroll
        for (int k8 = 0; k8 < 4; k8++) {
            const int kb = k8 * 8 + tig;
            uint32_t a[2][4], b[8][2];
#pragma unroll
            for (int mf = 0; mf < 2; mf++) {
                const int r0 = warp_m * 32 + mf * 16 + gid;
                a[mf][0] = f2tf(As[r0 * 36 + kb]);
                a[mf][1] = f2tf(As[(r0 + 8) * 36 + kb]);
                a[mf][2] = f2tf(As[r0 * 36 + kb + 4]);
                a[mf][3] = f2tf(As[(r0 + 8) * 36 + kb + 4]);
            }
#pragma unroll
            for (int nf = 0; nf < 8; nf++) {
                const int n = warp_n * 64 + nf * 8 + gid;
                b[nf][0] = f2tf(Bs[n * 36 + kb]);
                b[nf][1] = f2tf(Bs[n * 36 + kb + 4]);
            }
#pragma unroll
            for (int mf = 0; mf < 2; mf++)
#pragma unroll
                for (int nf = 0; nf < 8; nf++)
                    mma_tf32(c[mf][nf], a[mf], b[nf]);
        }
        __syncthreads();
    }

#pragma unroll
    for (int mf = 0; mf < 2; mf++) {
        const int row = m0 + warp_m * 32 + mf * 16 + gid;
#pragma unroll
        for (int nf = 0; nf < 8; nf++) {
            const int col = ncol0 + warp_n * 64 + nf * 8 + tig * 2;
            float v0 = c[mf][nf][0] * alpha, v1 = c[mf][nf][1] * alpha;
            float v2 = c[mf][nf][2] * alpha, v3 = c[mf][nf][3] * alpha;
            if (trunc) {
                v0 = __uint_as_float(f2tf(v0)); v1 = __uint_as_float(f2tf(v1));
                v2 = __uint_as_float(f2tf(v2)); v3 = __uint_as_float(f2tf(v3));
            }
            *(float2*)(C + row * 512 + col)       = make_float2(v0, v1);
            *(float2*)(C + (row + 8) * 512 + col) = make_float2(v2, v3);
        }
    }
}

// ===========================================================================
// relpos (unchanged from R4)
// ===========================================================================
#define RP_STRIDE 132
#define RP_SMEM_FLOATS (2 * 128 * RP_STRIDE)
#define RP_SMEM_BYTES  (RP_SMEM_FLOATS * 4)

__global__ __launch_bounds__(256) void relpos_gemm(
    const float* __restrict__ Q, const float* __restrict__ pw,
    const float* __restrict__ ph, float* __restrict__ RW,
    float* __restrict__ RH)
{
    extern __shared__ float sm[];
    float* As = sm;
    float* Ps = sm + 128 * RP_STRIDE;

    const int tid = threadIdx.x;
    const int tx  = tid & 15, ty = tid >> 4;
    const int rowbase = blockIdx.x * 128;

    for (int it = 0; it < 16; it++) {
        const int idx = it * 256 + tid;
        const int m = idx >> 5, k4 = idx & 31;
        float4 v = *(const float4*)(Q + (rowbase + m) * 128 + k4 * 4);
        As[(k4 * 4 + 0) * RP_STRIDE + m] = v.x;
        As[(k4 * 4 + 1) * RP_STRIDE + m] = v.y;
        As[(k4 * 4 + 2) * RP_STRIDE + m] = v.z;
        As[(k4 * 4 + 3) * RP_STRIDE + m] = v.w;
    }
    for (int idx = tid; idx < 128 * 128; idx += 256) {
        const int k = idx >> 7, c = idx & 127;
        float v = 0.f;
        if (c < 63)                  v = pw[k * 63 + c];
        else if (c >= 64 && c < 127) v = ph[k * 63 + (c - 64)];
        Ps[k * RP_STRIDE + c] = v;
    }
    __syncthreads();

    float acc[8][8];
#pragma unroll
    for (int i = 0; i < 8; i++)
#pragma unroll
        for (int j = 0; j < 8; j++) acc[i][j] = 0.f;

#pragma unroll 4
    for (int k = 0; k < 128; k++) {
        float4 a0 = *(const float4*)&As[k * RP_STRIDE + ty * 4];
        float4 a1 = *(const float4*)&As[k * RP_STRIDE + ty * 4 + 64];
        float4 b0 = *(const float4*)&Ps[k * RP_STRIDE + tx * 4];
        float4 b1 = *(const float4*)&Ps[k * RP_STRIDE + tx * 4 + 64];
        float av[8] = {a0.x, a0.y, a0.z, a0.w, a1.x, a1.y, a1.z, a1.w};
        float bv[8] = {b0.x, b0.y, b0.z, b0.w, b1.x, b1.y, b1.z, b1.w};
#pragma unroll
        for (int i = 0; i < 8; i++)
#pragma unroll
            for (int j = 0; j < 8; j++)
                acc[i][j] += av[i] * bv[j];
    }

#pragma unroll
    for (int i = 0; i < 8; i++) {
        const int m = ty * 4 + (i & 3) + ((i >> 2) << 6);
        const int row = rowbase + m;
#pragma unroll
        for (int j = 0; j < 8; j++) {
            const int cc = tx * 4 + (j & 3) + ((j >> 2) << 6);
            if (cc < 63)                   RW[row * 64 + cc]        = acc[i][j];
            else if (cc >= 64 && cc < 127) RH[row * 64 + (cc - 64)] = acc[i][j];
        }
    }
}

// ===========================================================================
// Flash attention v2: tf32 mma.sync + register softmax + relative bias.
// CTA: 128 query rows (8 warps x 16), BN=64 keys/iter, 256 threads.
// smem floats: Ks[64][132], Vs[128][68], Ps[128][68], RWt[128][64], RHs[128][64]
// ===========================================================================
#define AT_KS   0
#define AT_VS   8448
#define AT_PS   17152
#define AT_RWT  25856
#define AT_RHS  34048
#define AT_FLOATS 42240
#define AT_SMEM  (AT_FLOATS * 4)

__global__ __launch_bounds__(256, 1) void attn2(
    const float* __restrict__ Q, const float* __restrict__ Kg,
    const float* __restrict__ Vt, const float* __restrict__ RW,
    const float* __restrict__ RH, float* __restrict__ AO)
{
    extern __shared__ float sm[];
    float* Ks  = sm + AT_KS;
    float* Vs  = sm + AT_VS;
    float* Ps  = sm + AT_PS;
    float* RWt = sm + AT_RWT;
    float* RHs = sm + AT_RHS;
    const uint32_t sb = smem_u32(sm);

    const int tid = threadIdx.x, lane = tid & 31, wm = tid >> 5;
    const int gid = lane >> 2, tig = lane & 3;
    const int m0 = blockIdx.x * 128, h = blockIdx.y, b = blockIdx.z;

    // ---- prologue: bias tables into smem ----
    for (int i4 = tid; i4 < 128 * 16; i4 += 256) {        // RHs rows (float4)
        int r = i4 >> 4, c4 = i4 & 15;
        *(float4*)&RHs[r * 64 + c4 * 4] =
            *(const float4*)&RH[((b * Lq + m0 + r) * NHd + h) * 64 + c4 * 4];
    }
    for (int idx = tid; idx < 128 * 64; idx += 256) {      // RWt gather (iter-invariant)
        int r = idx >> 6, j = idx & 63;
        RWt[idx] = RW[((b * Lq + m0 + r) * NHd + h) * 64 + ((j & 31) - (r & 31) + 31)];
    }
    __syncthreads();

    // per-thread RW bias registers (rows gid, gid+8 of this warp's tile)
    const int row0 = wm * 16 + gid;
    float rwv[2][16];
#pragma unroll
    for (int i = 0; i < 2; i++) {
        const int r = row0 + 8 * i;
#pragma unroll
        for (int nf = 0; nf < 8; nf++) {
            rwv[i][nf * 2]     = RWt[r * 64 + nf * 8 + 2 * tig];
            rwv[i][nf * 2 + 1] = RWt[r * 64 + nf * 8 + 2 * tig + 1];
        }
    }
    const int ymr0 = (m0 + row0) >> 5;
    const int ymr1 = (m0 + row0 + 8) >> 5;

    // Q fragments (row-major A-frags, tf32), resident for the whole kernel
    const float* Qg = Q + (b * Lq + m0 + wm * 16) * Emb + h * KDim;
    uint32_t qf[16][4];
#pragma unroll
    for (int k8 = 0; k8 < 16; k8++) {
        qf[k8][0] = f2tf(Qg[gid * 512 + k8 * 8 + tig]);
        qf[k8][1] = f2tf(Qg[(gid + 8) * 512 + k8 * 8 + tig]);
        qf[k8][2] = f2tf(Qg[gid * 512 + k8 * 8 + tig + 4]);
        qf[k8][3] = f2tf(Qg[(gid + 8) * 512 + k8 * 8 + tig + 4]);
    }

    float acc[16][4];
#pragma unroll
    for (int n2 = 0; n2 < 16; n2++)
#pragma unroll
        for (int e = 0; e < 4; e++) acc[n2][e] = 0.f;
    float mrow[2] = {-3.0e38f, -3.0e38f};
    float lrow[2] = {0.f, 0.f};

    const float* Kbase = Kg + (b * Lq) * Emb + h * KDim;
    const float* Vbase = Vt + (b * NHd + h) * KDim * Lq;

    for (int n0 = 0; n0 < Lq; n0 += 64) {
        // ---- load K tile [64][128] and V tile [128][64] ----
#pragma unroll
        for (int it = 0; it < 8; it++) {
            const int idx4 = it * 256 + tid;
            const int key = idx4 >> 5, d4 = idx4 & 31;
            CP_ASYNC16(sb + (AT_KS + key * 132 + d4 * 4) * 4,
                       Kbase + (n0 + key) * 512 + d4 * 4);
        }
#pragma unroll
        for (int it = 0; it < 8; it++) {
            const int idx4 = it * 256 + tid;
            const int d = idx4 >> 4, k4 = idx4 & 15;
            CP_ASYNC16(sb + (AT_VS + d * 68 + k4 * 4) * 4,
                       Vbase + d * Lq + n0 + k4 * 4);
        }
        CP_COMMIT();
        CP_WAIT0();
        __syncthreads();

        // ---- S = Q K^T (K already tf32-rounded in global) ----
        float s[8][4];
#pragma unroll
        for (int nf = 0; nf < 8; nf++)
#pragma unroll
            for (int e = 0; e < 4; e++) s[nf][e] = 0.f;
#pragma unroll
        for (int k8 = 0; k8 < 16; k8++) {
#pragma unroll
            for (int nf = 0; nf < 8; nf++) {
                uint32_t bb[2];
                bb[0] = __float_as_uint(Ks[(nf * 8 + gid) * 132 + k8 * 8 + tig]);
                bb[1] = __float_as_uint(Ks[(nf * 8 + gid) * 132 + k8 * 8 + tig + 4]);
                mma_tf32(s[nf], qf[k8], bb);
            }
        }

        // ---- bias ----
        const int seg = n0 >> 5;
        float rh[2][2];
        rh[0][0] = RHs[row0 * 64 + seg - ymr0 + 31];
        rh[0][1] = RHs[row0 * 64 + seg + 1 - ymr0 + 31];
        rh[1][0] = RHs[(row0 + 8) * 64 + seg - ymr1 + 31];
        rh[1][1] = RHs[(row0 + 8) * 64 + seg + 1 - ymr1 + 31];
#pragma unroll
        for (int nf = 0; nf < 8; nf++) {
            const int u = nf >> 2;
            s[nf][0] += rwv[0][nf * 2]     + rh[0][u];
            s[nf][1] += rwv[0][nf * 2 + 1] + rh[0][u];
            s[nf][2] += rwv[1][nf * 2]     + rh[1][u];
            s[nf][3] += rwv[1][nf * 2 + 1] + rh[1][u];
        }

        // ---- online softmax (register resident; quad shuffles) ----
#pragma unroll
        for (int i = 0; i < 2; i++) {
            float mx = s[0][2 * i];
#pragma unroll
            for (int nf = 0; nf < 8; nf++) {
                mx = fmaxf(mx, s[nf][2 * i]);
                mx = fmaxf(mx, s[nf][2 * i + 1]);
            }
            mx = fmaxf(mx, __shfl_xor_sync(0xffffffffu, mx, 1));
            mx = fmaxf(mx, __shfl_xor_sync(0xffffffffu, mx, 2));
            const float mnew = fmaxf(mrow[i], mx);
            const float fsc = fexp2((mrow[i] - mnew) * L2E);
            mrow[i] = mnew;
            float sum = 0.f;
#pragma unroll
            for (int nf = 0; nf < 8; nf++) {
                float p0 = fexp2((s[nf][2 * i] - mnew) * L2E);
                float p1 = fexp2((s[nf][2 * i + 1] - mnew) * L2E);
                sum += p0 + p1;
                s[nf][2 * i] = p0;
                s[nf][2 * i + 1] = p1;
            }
            sum += __shfl_xor_sync(0xffffffffu, sum, 1);
            sum += __shfl_xor_sync(0xffffffffu, sum, 2);
            lrow[i] = lrow[i] * fsc + sum;
#pragma unroll
            for (int n2 = 0; n2 < 16; n2++) {
                acc[n2][2 * i]     *= fsc;
                acc[n2][2 * i + 1] *= fsc;
            }
        }

        // ---- P to smem (warp-private rows), tf32-rounded ----
#pragma unroll
        for (int nf = 0; nf < 8; nf++) {
            Ps[row0 * 68 + nf * 8 + 2 * tig]           = __uint_as_float(f2tf(s[nf][0]));
            Ps[row0 * 68 + nf * 8 + 2 * tig + 1]       = __uint_as_float(f2tf(s[nf][1]));
            Ps[(row0 + 8) * 68 + nf * 8 + 2 * tig]     = __uint_as_float(f2tf(s[nf][2]));
            Ps[(row0 + 8) * 68 + nf * 8 + 2 * tig + 1] = __uint_as_float(f2tf(s[nf][3]));
        }
        __syncwarp();

        // ---- acc += P @ V (V already tf32-rounded) ----
#pragma unroll
        for (int k8 = 0; k8 < 8; k8++) {
            uint32_t pa[4];
            pa[0] = __float_as_uint(Ps[row0 * 68 + k8 * 8 + tig]);
            pa[1] = __float_as_uint(Ps[(row0 + 8) * 68 + k8 * 8 + tig]);
            pa[2] = __float_as_uint(Ps[row0 * 68 + k8 * 8 + tig + 4]);
            pa[3] = __float_as_uint(Ps[(row0 + 8) * 68 + k8 * 8 + tig + 4]);
#pragma unroll
            for (int n2 = 0; n2 < 16; n2++) {
                uint32_t bb[2];
                bb[0] = __float_as_uint(Vs[(n2 * 8 + gid) * 68 + k8 * 8 + tig]);
                bb[1] = __float_as_uint(Vs[(n2 * 8 + gid) * 68 + k8 * 8 + tig + 4]);
                mma_tf32(acc[n2], pa, bb);
            }
        }
        __syncthreads();   // all warps done with Ks/Vs before next iter's loads
    }

    // ---- epilogue: normalize and write AO[b,m,h,d] ----
    const float inv0 = 1.f / lrow[0];
    const float inv1 = 1.f / lrow[1];
    const int gm0 = b * Lq + m0 + wm * 16 + gid;
#pragma unroll
    for (int n2 = 0; n2 < 16; n2++) {
        const int col = n2 * 8 + 2 * tig;
        *(float2*)&AO[(gm0 * NHd + h) * KDim + col] =
            make_float2(acc[n2][0] * inv0, acc[n2][1] * inv0);
        *(float2*)&AO[((gm0 + 8) * NHd + h) * KDim + col] =
            make_float2(acc[n2][2] * inv1, acc[n2][3] * inv1);
    }
}

// ---------------------------------------------------------------------------
extern "C" void kernel_launch(void* const* d_in, const int* in_sizes, int n_in,
                              void* d_out, int out_size)
{
    (void)in_sizes; (void)n_in; (void)out_size;
    const float* x  = (const float*)d_in[0];
    const float* Wq = (const float*)d_in[1];
    const float* Wk = (const float*)d_in[2];
    const float* Wv = (const float*)d_in[3];
    const float* Wo = (const float*)d_in[4];
    const float* pw = (const float*)d_in[5];
    const float* ph = (const float*)d_in[6];
    float* out = (float*)d_out;

    float *q, *k, *v, *vt, *ao, *rw, *rh, *wt, *wto;
    cudaGetSymbolAddress((void**)&q,   g_Q);
    cudaGetSymbolAddress((void**)&k,   g_K);
    cudaGetSymbolAddress((void**)&v,   g_V);
    cudaGetSymbolAddress((void**)&vt,  g_Vt);
    cudaGetSymbolAddress((void**)&ao,  g_AO);
    cudaGetSymbolAddress((void**)&rw,  g_RW);
    cudaGetSymbolAddress((void**)&rh,  g_RH);
    cudaGetSymbolAddress((void**)&wt,  g_Wt);
    cudaGetSymbolAddress((void**)&wto, g_WtO);

    const float scale = 0.08838834764831845f;  // 1/sqrt(128)

    cudaFuncSetAttribute(gemm_mma,
                         cudaFuncAttributeMaxDynamicSharedMemorySize,
                         GEMM_SMEM_BYTES);
    cudaFuncSetAttribute(relpos_gemm,
                         cudaFuncAttributeMaxDynamicSharedMemorySize,
                         RP_SMEM_BYTES);
    cudaFuncSetAttribute(attn2,
                         cudaFuncAttributeMaxDynamicSharedMemorySize,
                         AT_SMEM);

    transpose_w<<<dim3(16, 16, 4), 256>>>(Wq, Wk, Wv, Wo, wt, wto);

    gemm_mma<<<dim3(12, 64), 256, GEMM_SMEM_BYTES>>>(x, wt, q, k, v, scale);

    vtrans<<<dim3(32, 4, 32), 256>>>(v, vt);

    relpos_gemm<<<256, 256, RP_SMEM_BYTES>>>(q, pw, ph, rw, rh);

    attn2<<<dim3(8, NHd, Bz), 256, AT_SMEM>>>(q, k, vt, rw, rh, ao);

    gemm_mma<<<dim3(4, 64), 256, GEMM_SMEM_BYTES>>>(ao, wto, out, out, out, 1.0f);
}

// round 6
// speedup vs baseline: 4.2564x; 1.3323x over previous
#include <cuda_runtime.h>
#include <cstdint>

// Problem constants
#define Bz    8
#define HHg   32
#define WWg   32
#define Lq    1024          // HHg*WWg
#define Cin   512
#define NHd   4
#define KDim  128
#define Emb   512           // NHd*KDim
#define Mrows 8192          // Bz*Lq

// Scratch (device globals: allocation-free rule)
__device__ float g_Q  [Mrows * Emb];
__device__ float g_K  [Mrows * Emb];
__device__ float g_V  [Mrows * Emb];
__device__ float g_Vt [Bz * NHd * KDim * Lq];  // V transposed: [b][h][d][key]
__device__ float g_AO [Mrows * Emb];
__device__ float g_RW [Mrows * NHd * 64];   // 63 used, padded to 64
__device__ float g_RH [Mrows * NHd * 64];
__device__ float g_Wt [3 * Emb * Cin];      // transposed Wq|Wk|Wv, [1536][512]
__device__ float g_WtO[Emb * Emb];          // transposed Wo, [512][512]
__device__ float g_Pt [128 * 128];          // padded pos tables, [r][d]

// ===========================================================================
// Helpers
// ===========================================================================
__device__ __forceinline__ uint32_t smem_u32(const void* p) {
    uint32_t a;
    asm("{ .reg .u64 t; cvta.to.shared.u64 t, %1; cvt.u32.u64 %0, t; }"
        : "=r"(a) : "l"(p));
    return a;
}
__device__ __forceinline__ uint32_t f2tf(float f) {
    uint32_t r;
    asm("cvt.rna.tf32.f32 %0, %1;" : "=r"(r) : "f"(f));
    return r;
}
#define CP_ASYNC16(dst, src) \
    asm volatile("cp.async.cg.shared.global [%0], [%1], 16;" \
                 :: "r"(dst), "l"(src) : "memory")
#define CP_COMMIT() asm volatile("cp.async.commit_group;" ::: "memory")
#define CP_WAIT1()  asm volatile("cp.async.wait_group 1;" ::: "memory")
#define CP_WAIT0()  asm volatile("cp.async.wait_group 0;" ::: "memory")

__device__ __forceinline__ void mma_tf32(float* c, const uint32_t* a,
                                         const uint32_t* b) {
    asm volatile(
        "mma.sync.aligned.m16n8k8.row.col.f32.tf32.tf32.f32 "
        "{%0,%1,%2,%3}, {%4,%5,%6,%7}, {%8,%9}, {%0,%1,%2,%3};"
        : "+f"(c[0]), "+f"(c[1]), "+f"(c[2]), "+f"(c[3])
        : "r"(a[0]), "r"(a[1]), "r"(a[2]), "r"(a[3]), "r"(b[0]), "r"(b[1]));
}

// Fast exp2 on the FMA pipe (x <= 0, clamped): rint-split + deg-5 Taylor.
__device__ __forceinline__ float fexp2(float x) {
    x = fmaxf(x, -120.f);
    float r = rintf(x);
    float f = x - r;                       // f in [-0.5, 0.5]
    float p =              0.0013333558f;
    p = fmaf(p, f, 0.0096181291f);
    p = fmaf(p, f, 0.0555041087f);
    p = fmaf(p, f, 0.2402265069f);
    p = fmaf(p, f, 0.6931471806f);
    p = fmaf(p, f, 1.0f);
    int e = (int)r;
    return p * __int_as_float((e + 127) << 23);
}
#define L2E 1.4426950408889634f

// ===========================================================================
// Weight transpose: Wt[n][k] = W[k][n] for Wq|Wk|Wv (fused) and Wo.
// ===========================================================================
__global__ __launch_bounds__(256) void transpose_w(
    const float* __restrict__ Wq, const float* __restrict__ Wk,
    const float* __restrict__ Wv, const float* __restrict__ Wo,
    float* __restrict__ Wt, float* __restrict__ WtO)
{
    __shared__ float t[32][33];
    const int z = blockIdx.z;
    const float* W = (z == 0) ? Wq : (z == 1) ? Wk : (z == 2) ? Wv : Wo;
    float* O = (z == 3) ? WtO : (Wt + z * Emb * Cin);
    const int tx = threadIdx.x & 31, ty = threadIdx.x >> 5;  // 32 x 8
    const int k0 = blockIdx.y * 32, n0 = blockIdx.x * 32;
#pragma unroll
    for (int i = 0; i < 4; i++)
        t[ty + i * 8][tx] = W[(k0 + ty + i * 8) * 512 + n0 + tx];
    __syncthreads();
#pragma unroll
    for (int i = 0; i < 4; i++)
        O[(n0 + ty + i * 8) * 512 + k0 + tx] = t[tx][ty + i * 8];
}

// ===========================================================================
// Build Pt[128][128]: rows 0-62 = pos_emb_w^T, rows 64-126 = pos_emb_h^T.
// ===========================================================================
__global__ __launch_bounds__(256) void build_pt(
    const float* __restrict__ pw, const float* __restrict__ ph,
    float* __restrict__ Pt)
{
    const int idx = blockIdx.x * 256 + threadIdx.x;   // 16384 total
    const int r = idx >> 7, d = idx & 127;
    float v = 0.f;
    if (r < 63)                  v = pw[d * 63 + r];
    else if (r >= 64 && r < 127) v = ph[d * 63 + (r - 64)];
    Pt[idx] = v;
}

// ===========================================================================
// V transpose per (b,h): Vt[b][h][d][key] = V[b*1024+key][h*128+d], tf32.
// ===========================================================================
__global__ __launch_bounds__(256) void vtrans(
    const float* __restrict__ V, float* __restrict__ Vt)
{
    __shared__ float t[32][33];
    const int bh = blockIdx.z;
    const int b = bh >> 2, h = bh & 3;
    const int k0 = blockIdx.x * 32, d0 = blockIdx.y * 32;
    const int tx = threadIdx.x & 31, ty = threadIdx.x >> 5;
#pragma unroll
    for (int i = 0; i < 4; i++)
        t[ty + i * 8][tx] = V[(b * Lq + k0 + ty + i * 8) * Emb + h * KDim + d0 + tx];
    __syncthreads();
#pragma unroll
    for (int i = 0; i < 4; i++)
        Vt[(bh * KDim + d0 + ty + i * 8) * Lq + k0 + tx] =
            __uint_as_float(f2tf(t[tx][ty + i * 8]));
}

// ===========================================================================
// tf32 mma.sync GEMM (K output pre-truncated to tf32)
// ===========================================================================
#define GEMM_STAGE_FLOATS (2 * 128 * 36)
#define GEMM_SMEM_BYTES   (2 * GEMM_STAGE_FLOATS * 4)

__global__ __launch_bounds__(256) void gemm_mma(
    const float* __restrict__ A, const float* __restrict__ Bt,
    float* __restrict__ C0, float* __restrict__ C1, float* __restrict__ C2,
    float alpha0)
{
    extern __shared__ float smf[];
    const uint32_t sb = smem_u32(smf);
    const int tid  = threadIdx.x;
    const int lane = tid & 31, wid = tid >> 5;
    const int warp_m = wid & 3, warp_n = wid >> 2;
    const int gid = lane >> 2, tig = lane & 3;

    const int bx   = blockIdx.x;
    const int outi = bx >> 2;
    float* C = (outi == 0) ? C0 : (outi == 1) ? C1 : C2;
    const float alpha = (outi == 0) ? alpha0 : 1.0f;
    const bool trunc = (outi == 1);
    const int m0    = blockIdx.y * 128;
    const int nrow0 = bx * 128;
    const int ncol0 = (bx & 3) * 128;

    const float* Ab = A  + m0 * 512;
    const float* Bb = Bt + nrow0 * 512;

    float c[2][8][4];
#pragma unroll
    for (int mf = 0; mf < 2; mf++)
#pragma unroll
        for (int nf = 0; nf < 8; nf++)
#pragma unroll
            for (int e = 0; e < 4; e++) c[mf][nf][e] = 0.f;

    auto issue = [&](int kc, int s) {
#pragma unroll
        for (int it = 0; it < 4; it++) {
            const int idx4 = it * 256 + tid;
            const int m  = idx4 >> 3;
            const int k4 = idx4 & 7;
            const uint32_t so = sb + s * (GEMM_STAGE_FLOATS * 4)
                                + m * 144 + k4 * 16;
            CP_ASYNC16(so,         Ab + m * 512 + kc * 32 + k4 * 4);
            CP_ASYNC16(so + 18432, Bb + m * 512 + kc * 32 + k4 * 4);
        }
        CP_COMMIT();
    };

    issue(0, 0);

    for (int kc = 0; kc < 16; kc++) {
        const int s = kc & 1;
        if (kc < 15) { issue(kc + 1, s ^ 1); CP_WAIT1(); }
        else         { CP_WAIT0(); }
        __syncthreads();

        const float* As = smf + s * GEMM_STAGE_FLOATS;
        const float* Bs = As + 128 * 36;

#pragma unroll
        for (int k8 = 0; k8 < 4; k8++) {
            const int kb = k8 * 8 + tig;
            uint32_t a[2][4], b[8][2];
#pragma unroll
            for (int mf = 0; mf < 2; mf++) {
                const int r0 = warp_m * 32 + mf * 16 + gid;
                a[mf][0] = f2tf(As[r0 * 36 + kb]);
                a[mf][1] = f2tf(As[(r0 + 8) * 36 + kb]);
                a[mf][2] = f2tf(As[r0 * 36 + kb + 4]);
                a[mf][3] = f2tf(As[(r0 + 8) * 36 + kb + 4]);
            }
#pragma unroll
            for (int nf = 0; nf < 8; nf++) {
                const int n = warp_n * 64 + nf * 8 + gid;
                b[nf][0] = f2tf(Bs[n * 36 + kb]);
                b[nf][1] = f2tf(Bs[n * 36 + kb + 4]);
            }
#pragma unroll
            for (int mf = 0; mf < 2; mf++)
#pragma unroll
                for (int nf = 0; nf < 8; nf++)
                    mma_tf32(c[mf][nf], a[mf], b[nf]);
        }
        __syncthreads();
    }

#pragma unroll
    for (int mf = 0; mf < 2; mf++) {
        const int row = m0 + warp_m * 32 + mf * 16 + gid;
#pragma unroll
        for (int nf = 0; nf < 8; nf++) {
            const int col = ncol0 + warp_n * 64 + nf * 8 + tig * 2;
            float v0 = c[mf][nf][0] * alpha, v1 = c[mf][nf][1] * alpha;
            float v2 = c[mf][nf][2] * alpha, v3 = c[mf][nf][3] * alpha;
            if (trunc) {
                v0 = __uint_as_float(f2tf(v0)); v1 = __uint_as_float(f2tf(v1));
                v2 = __uint_as_float(f2tf(v2)); v3 = __uint_as_float(f2tf(v3));
            }
            *(float2*)(C + row * 512 + col)       = make_float2(v0, v1);
            *(float2*)(C + (row + 8) * 512 + col) = make_float2(v2, v3);
        }
    }
}

// ===========================================================================
// relpos via tf32 mma: [32768,128] @ Pt[128,128]^T -> RW|RH (split store).
// grid 256 m-tiles, 8 warps: warp_m = wid&3 (rows), warp_n = wid>>2 (2 x 64).
// ===========================================================================
#define RPM_STAGE_FLOATS (2 * 128 * 36)
#define RPM_SMEM_BYTES   (2 * RPM_STAGE_FLOATS * 4)

__global__ __launch_bounds__(256) void relpos_mma(
    const float* __restrict__ Q, const float* __restrict__ Pt,
    float* __restrict__ RW, float* __restrict__ RH)
{
    extern __shared__ float smf[];
    const uint32_t sb = smem_u32(smf);
    const int tid  = threadIdx.x;
    const int lane = tid & 31, wid = tid >> 5;
    const int warp_m = wid & 3, warp_n = wid >> 2;
    const int gid = lane >> 2, tig = lane & 3;
    const int m0 = blockIdx.x * 128;

    const float* Ab = Q + m0 * 128;     // flat [32768][128]

    float c[2][8][4];
#pragma unroll
    for (int mf = 0; mf < 2; mf++)
#pragma unroll
        for (int nf = 0; nf < 8; nf++)
#pragma unroll
            for (int e = 0; e < 4; e++) c[mf][nf][e] = 0.f;

    auto issue = [&](int kc, int s) {
#pragma unroll
        for (int it = 0; it < 4; it++) {
            const int idx4 = it * 256 + tid;
            const int m  = idx4 >> 3;
            const int k4 = idx4 & 7;
            const uint32_t so = sb + s * (RPM_STAGE_FLOATS * 4)
                                + m * 144 + k4 * 16;
            CP_ASYNC16(so,         Ab + m * 128 + kc * 32 + k4 * 4);
            CP_ASYNC16(so + 18432, Pt + m * 128 + kc * 32 + k4 * 4);
        }
        CP_COMMIT();
    };

    issue(0, 0);
    for (int kc = 0; kc < 4; kc++) {
        const int s = kc & 1;
        if (kc < 3) { issue(kc + 1, s ^ 1); CP_WAIT1(); }
        else        { CP_WAIT0(); }
        __syncthreads();

        const float* As = smf + s * RPM_STAGE_FLOATS;
        const float* Bs = As + 128 * 36;

#pragma unroll
        for (int k8 = 0; k8 < 4; k8++) {
            const int kb = k8 * 8 + tig;
            uint32_t a[2][4], b[8][2];
#pragma unroll
            for (int mf = 0; mf < 2; mf++) {
                const int r0 = warp_m * 32 + mf * 16 + gid;
                a[mf][0] = f2tf(As[r0 * 36 + kb]);
                a[mf][1] = f2tf(As[(r0 + 8) * 36 + kb]);
                a[mf][2] = f2tf(As[r0 * 36 + kb + 4]);
                a[mf][3] = f2tf(As[(r0 + 8) * 36 + kb + 4]);
            }
#pragma unroll
            for (int nf = 0; nf < 8; nf++) {
                const int n = warp_n * 64 + nf * 8 + gid;
                b[nf][0] = f2tf(Bs[n * 36 + kb]);
                b[nf][1] = f2tf(Bs[n * 36 + kb + 4]);
            }
#pragma unroll
            for (int mf = 0; mf < 2; mf++)
#pragma unroll
                for (int nf = 0; nf < 8; nf++)
                    mma_tf32(c[mf][nf], a[mf], b[nf]);
        }
        __syncthreads();
    }

    auto put = [&](int row, int col, float v) {
        if (col < 63)                  RW[row * 64 + col] = v;
        else if (col >= 64 && col < 127) RH[row * 64 + col - 64] = v;
    };
#pragma unroll
    for (int mf = 0; mf < 2; mf++) {
        const int row = m0 + warp_m * 32 + mf * 16 + gid;
#pragma unroll
        for (int nf = 0; nf < 8; nf++) {
            const int col = warp_n * 64 + nf * 8 + tig * 2;
            put(row,     col,     c[mf][nf][0]);
            put(row,     col + 1, c[mf][nf][1]);
            put(row + 8, col,     c[mf][nf][2]);
            put(row + 8, col + 1, c[mf][nf][3]);
        }
    }
}

// ===========================================================================
// Flash attention: tf32 mma.sync, register softmax, double-buffered K/V.
// smem floats: Ks[2][64*132], Vs[2][128*68], Ps[128*68], RHs[128*64]
// ===========================================================================
#define AT_KS0 0
#define AT_KS1 8448
#define AT_VS0 16896
#define AT_VS1 25600
#define AT_PS  34304
#define AT_RHS 43008
#define AT_FLOATS 51200
#define AT_SMEM  (AT_FLOATS * 4)      // 204800 B

__global__ __launch_bounds__(256, 1) void attn2(
    const float* __restrict__ Q, const float* __restrict__ Kg,
    const float* __restrict__ Vt, const float* __restrict__ RW,
    const float* __restrict__ RH, float* __restrict__ AO)
{
    extern __shared__ float sm[];
    float* Ps  = sm + AT_PS;
    float* RHs = sm + AT_RHS;
    const uint32_t sb = smem_u32(sm);

    const int tid = threadIdx.x, lane = tid & 31, wm = tid >> 5;
    const int gid = lane >> 2, tig = lane & 3;
    const int m0 = blockIdx.x * 128, h = blockIdx.y, b = blockIdx.z;

    // RH rows for this tile -> smem
    for (int i4 = tid; i4 < 128 * 16; i4 += 256) {
        int r = i4 >> 4, c4 = i4 & 15;
        *(float4*)&RHs[r * 64 + c4 * 4] =
            *(const float4*)&RH[((b * Lq + m0 + r) * NHd + h) * 64 + c4 * 4];
    }

    // RW bias registers direct from global (iter-invariant gather)
    const int row0 = wm * 16 + gid;
    float rwv[2][16];
#pragma unroll
    for (int i = 0; i < 2; i++) {
        const int r = row0 + 8 * i;
        const float* RWr = RW + ((b * Lq + m0 + r) * NHd + h) * 64 - (r & 31) + 31;
#pragma unroll
        for (int nf = 0; nf < 8; nf++) {
            rwv[i][nf * 2]     = RWr[((nf * 8 + 2 * tig) & 31)];
            rwv[i][nf * 2 + 1] = RWr[((nf * 8 + 2 * tig + 1) & 31)];
        }
    }
    const int ymr0 = (m0 + row0) >> 5;
    const int ymr1 = (m0 + row0 + 8) >> 5;

    // Q fragments
    const float* Qg = Q + (b * Lq + m0 + wm * 16) * Emb + h * KDim;
    uint32_t qf[16][4];
#pragma unroll
    for (int k8 = 0; k8 < 16; k8++) {
        qf[k8][0] = f2tf(Qg[gid * 512 + k8 * 8 + tig]);
        qf[k8][1] = f2tf(Qg[(gid + 8) * 512 + k8 * 8 + tig]);
        qf[k8][2] = f2tf(Qg[gid * 512 + k8 * 8 + tig + 4]);
        qf[k8][3] = f2tf(Qg[(gid + 8) * 512 + k8 * 8 + tig + 4]);
    }

    float acc[16][4];
#pragma unroll
    for (int n2 = 0; n2 < 16; n2++)
#pragma unroll
        for (int e = 0; e < 4; e++) acc[n2][e] = 0.f;
    float mrow[2] = {-3.0e38f, -3.0e38f};
    float lrow[2] = {0.f, 0.f};

    const float* Kbase = Kg + (b * Lq) * Emb + h * KDim;
    const float* Vbase = Vt + (b * NHd + h) * KDim * Lq;

    auto load_tile = [&](int n0, int st) {
#pragma unroll
        for (int it = 0; it < 8; it++) {
            const int idx4 = it * 256 + tid;
            const int key = idx4 >> 5, d4 = idx4 & 31;
            CP_ASYNC16(sb + (AT_KS0 + st * 8448 + key * 132 + d4 * 4) * 4,
                       Kbase + (n0 + key) * 512 + d4 * 4);
        }
#pragma unroll
        for (int it = 0; it < 8; it++) {
            const int idx4 = it * 256 + tid;
            const int d = idx4 >> 4, k4 = idx4 & 15;
            CP_ASYNC16(sb + (AT_VS0 + st * 8704 + d * 68 + k4 * 4) * 4,
                       Vbase + d * Lq + n0 + k4 * 4);
        }
        CP_COMMIT();
    };

    load_tile(0, 0);

    for (int it = 0; it < 16; it++) {
        const int n0 = it * 64;
        const int st = it & 1;
        if (it < 15) { load_tile(n0 + 64, st ^ 1); CP_WAIT1(); }
        else         { CP_WAIT0(); }
        __syncthreads();

        const float* Ks = sm + AT_KS0 + st * 8448;
        const float* Vs = sm + AT_VS0 + st * 8704;

        // S = Q K^T
        float s[8][4];
#pragma unroll
        for (int nf = 0; nf < 8; nf++)
#pragma unroll
            for (int e = 0; e < 4; e++) s[nf][e] = 0.f;
#pragma unroll
        for (int k8 = 0; k8 < 16; k8++) {
#pragma unroll
            for (int nf = 0; nf < 8; nf++) {
                uint32_t bb[2];
                bb[0] = __float_as_uint(Ks[(nf * 8 + gid) * 132 + k8 * 8 + tig]);
                bb[1] = __float_as_uint(Ks[(nf * 8 + gid) * 132 + k8 * 8 + tig + 4]);
                mma_tf32(s[nf], qf[k8], bb);
            }
        }

        // bias
        const int seg = n0 >> 5;
        float rh[2][2];
        rh[0][0] = RHs[row0 * 64 + seg - ymr0 + 31];
        rh[0][1] = RHs[row0 * 64 + seg + 1 - ymr0 + 31];
        rh[1][0] = RHs[(row0 + 8) * 64 + seg - ymr1 + 31];
        rh[1][1] = RHs[(row0 + 8) * 64 + seg + 1 - ymr1 + 31];
#pragma unroll
        for (int nf = 0; nf < 8; nf++) {
            const int u = nf >> 2;
            s[nf][0] += rwv[0][nf * 2]     + rh[0][u];
            s[nf][1] += rwv[0][nf * 2 + 1] + rh[0][u];
            s[nf][2] += rwv[1][nf * 2]     + rh[1][u];
            s[nf][3] += rwv[1][nf * 2 + 1] + rh[1][u];
        }

        // online softmax
#pragma unroll
        for (int i = 0; i < 2; i++) {
            float mx = s[0][2 * i];
#pragma unroll
            for (int nf = 0; nf < 8; nf++) {
                mx = fmaxf(mx, s[nf][2 * i]);
                mx = fmaxf(mx, s[nf][2 * i + 1]);
            }
            mx = fmaxf(mx, __shfl_xor_sync(0xffffffffu, mx, 1));
            mx = fmaxf(mx, __shfl_xor_sync(0xffffffffu, mx, 2));
            const float mnew = fmaxf(mrow[i], mx);
            const float fsc = fexp2((mrow[i] - mnew) * L2E);
            mrow[i] = mnew;
            float sum = 0.f;
#pragma unroll
            for (int nf = 0; nf < 8; nf++) {
                float p0 = fexp2((s[nf][2 * i] - mnew) * L2E);
                float p1 = fexp2((s[nf][2 * i + 1] - mnew) * L2E);
                sum += p0 + p1;
                s[nf][2 * i] = p0;
                s[nf][2 * i + 1] = p1;
            }
            sum += __shfl_xor_sync(0xffffffffu, sum, 1);
            sum += __shfl_xor_sync(0xffffffffu, sum, 2);
            lrow[i] = lrow[i] * fsc + sum;
#pragma unroll
            for (int n2 = 0; n2 < 16; n2++) {
                acc[n2][2 * i]     *= fsc;
                acc[n2][2 * i + 1] *= fsc;
            }
        }

        // P to smem (warp-private rows)
#pragma unroll
        for (int nf = 0; nf < 8; nf++) {
            Ps[row0 * 68 + nf * 8 + 2 * tig]           = __uint_as_float(f2tf(s[nf][0]));
            Ps[row0 * 68 + nf * 8 + 2 * tig + 1]       = __uint_as_float(f2tf(s[nf][1]));
            Ps[(row0 + 8) * 68 + nf * 8 + 2 * tig]     = __uint_as_float(f2tf(s[nf][2]));
            Ps[(row0 + 8) * 68 + nf * 8 + 2 * tig + 1] = __uint_as_float(f2tf(s[nf][3]));
        }
        __syncwarp();

        // acc += P @ V
#pragma unroll
        for (int k8 = 0; k8 < 8; k8++) {
            uint32_t pa[4];
            pa[0] = __float_as_uint(Ps[row0 * 68 + k8 * 8 + tig]);
            pa[1] = __float_as_uint(Ps[(row0 + 8) * 68 + k8 * 8 + tig]);
            pa[2] = __float_as_uint(Ps[row0 * 68 + k8 * 8 + tig + 4]);
            pa[3] = __float_as_uint(Ps[(row0 + 8) * 68 + k8 * 8 + tig + 4]);
#pragma unroll
            for (int n2 = 0; n2 < 16; n2++) {
                uint32_t bb[2];
                bb[0] = __float_as_uint(Vs[(n2 * 8 + gid) * 68 + k8 * 8 + tig]);
                bb[1] = __float_as_uint(Vs[(n2 * 8 + gid) * 68 + k8 * 8 + tig + 4]);
                mma_tf32(acc[n2], pa, bb);
            }
        }
        __syncthreads();   // buffer st free before iter it+1 overwrites it
    }

    // epilogue
    const float inv0 = 1.f / lrow[0];
    const float inv1 = 1.f / lrow[1];
    const int gm0 = b * Lq + m0 + wm * 16 + gid;
#pragma unroll
    for (int n2 = 0; n2 < 16; n2++) {
        const int col = n2 * 8 + 2 * tig;
        *(float2*)&AO[(gm0 * NHd + h) * KDim + col] =
            make_float2(acc[n2][0] * inv0, acc[n2][1] * inv0);
        *(float2*)&AO[((gm0 + 8) * NHd + h) * KDim + col] =
            make_float2(acc[n2][2] * inv1, acc[n2][3] * inv1);
    }
}

// ---------------------------------------------------------------------------
extern "C" void kernel_launch(void* const* d_in, const int* in_sizes, int n_in,
                              void* d_out, int out_size)
{
    (void)in_sizes; (void)n_in; (void)out_size;
    const float* x  = (const float*)d_in[0];
    const float* Wq = (const float*)d_in[1];
    const float* Wk = (const float*)d_in[2];
    const float* Wv = (const float*)d_in[3];
    const float* Wo = (const float*)d_in[4];
    const float* pw = (const float*)d_in[5];
    const float* ph = (const float*)d_in[6];
    float* out = (float*)d_out;

    float *q, *k, *v, *vt, *ao, *rw, *rh, *wt, *wto, *pt;
    cudaGetSymbolAddress((void**)&q,   g_Q);
    cudaGetSymbolAddress((void**)&k,   g_K);
    cudaGetSymbolAddress((void**)&v,   g_V);
    cudaGetSymbolAddress((void**)&vt,  g_Vt);
    cudaGetSymbolAddress((void**)&ao,  g_AO);
    cudaGetSymbolAddress((void**)&rw,  g_RW);
    cudaGetSymbolAddress((void**)&rh,  g_RH);
    cudaGetSymbolAddress((void**)&wt,  g_Wt);
    cudaGetSymbolAddress((void**)&wto, g_WtO);
    cudaGetSymbolAddress((void**)&pt,  g_Pt);

    const float scale = 0.08838834764831845f;  // 1/sqrt(128)

    cudaFuncSetAttribute(gemm_mma,
                         cudaFuncAttributeMaxDynamicSharedMemorySize,
                         GEMM_SMEM_BYTES);
    cudaFuncSetAttribute(relpos_mma,
                         cudaFuncAttributeMaxDynamicSharedMemorySize,
                         RPM_SMEM_BYTES);
    cudaFuncSetAttribute(attn2,
                         cudaFuncAttributeMaxDynamicSharedMemorySize,
                         AT_SMEM);

    transpose_w<<<dim3(16, 16, 4), 256>>>(Wq, Wk, Wv, Wo, wt, wto);
    build_pt<<<64, 256>>>(pw, ph, pt);

    gemm_mma<<<dim3(12, 64), 256, GEMM_SMEM_BYTES>>>(x, wt, q, k, v, scale);

    vtrans<<<dim3(32, 4, 32), 256>>>(v, vt);

    relpos_mma<<<256, 256, RPM_SMEM_BYTES>>>(q, pt, rw, rh);

    attn2<<<dim3(8, NHd, Bz), 256, AT_SMEM>>>(q, k, vt, rw, rh, ao);

    gemm_mma<<<dim3(4, 64), 256, GEMM_SMEM_BYTES>>>(ao, wto, out, out, out, 1.0f);
}

// round 7
// speedup vs baseline: 7.4391x; 1.7478x over previous
#include <cuda_runtime.h>
#include <cuda_fp16.h>
#include <cstdint>

// Problem constants
#define Bz    8
#define HHg   32
#define WWg   32
#define Lq    1024          // HHg*WWg
#define Cin   512
#define NHd   4
#define KDim  128
#define Emb   512           // NHd*KDim
#define Mrows 8192          // Bz*Lq

// Scratch (device globals: allocation-free rule)
__device__ __half g_Xh  [Mrows * Cin];
__device__ __half g_Qh  [Mrows * Emb];
__device__ __half g_Kh  [Mrows * Emb];
__device__ __half g_Vh  [Mrows * Emb];
__device__ __half g_Vth [Bz * NHd * KDim * Lq];  // [b][h][d][key]
__device__ __half g_AOh [Mrows * Emb];
__device__ float  g_RW  [Mrows * NHd * 64];      // 63 used, padded
__device__ float  g_RH  [Mrows * NHd * 64];
__device__ __half g_Wth [3 * Emb * Cin];         // transposed Wq|Wk|Wv [1536][512]
__device__ __half g_WtOh[Emb * Emb];             // transposed Wo [512][512]
__device__ __half g_Pth [128 * 128];             // padded pos tables [r][d]

// ===========================================================================
// Helpers
// ===========================================================================
__device__ __forceinline__ uint32_t smem_u32(const void* p) {
    uint32_t a;
    asm("{ .reg .u64 t; cvta.to.shared.u64 t, %1; cvt.u32.u64 %0, t; }"
        : "=r"(a) : "l"(p));
    return a;
}
#define CP_ASYNC16(dst, src) \
    asm volatile("cp.async.cg.shared.global [%0], [%1], 16;" \
                 :: "r"(dst), "l"(src) : "memory")
#define CP_COMMIT() asm volatile("cp.async.commit_group;" ::: "memory")
#define CP_WAIT1()  asm volatile("cp.async.wait_group 1;" ::: "memory")
#define CP_WAIT0()  asm volatile("cp.async.wait_group 0;" ::: "memory")

#define LDSM_X4(r0, r1, r2, r3, addr) \
    asm volatile("ldmatrix.sync.aligned.m8n8.x4.shared.b16 {%0,%1,%2,%3}, [%4];" \
        : "=r"(r0), "=r"(r1), "=r"(r2), "=r"(r3) : "r"(addr))

__device__ __forceinline__ void mma_f16(float* c, const uint32_t* a,
                                        uint32_t b0, uint32_t b1) {
    asm volatile(
        "mma.sync.aligned.m16n8k16.row.col.f32.f16.f16.f32 "
        "{%0,%1,%2,%3}, {%4,%5,%6,%7}, {%8,%9}, {%0,%1,%2,%3};"
        : "+f"(c[0]), "+f"(c[1]), "+f"(c[2]), "+f"(c[3])
        : "r"(a[0]), "r"(a[1]), "r"(a[2]), "r"(a[3]), "r"(b0), "r"(b1));
}

// Fast exp2 on the FMA pipe
__device__ __forceinline__ float fexp2(float x) {
    x = fmaxf(x, -120.f);
    float r = rintf(x);
    float f = x - r;
    float p =              0.0013333558f;
    p = fmaf(p, f, 0.0096181291f);
    p = fmaf(p, f, 0.0555041087f);
    p = fmaf(p, f, 0.2402265069f);
    p = fmaf(p, f, 0.6931471806f);
    p = fmaf(p, f, 1.0f);
    int e = (int)r;
    return p * __int_as_float((e + 127) << 23);
}
#define L2E 1.4426950408889634f

// ===========================================================================
// x -> fp16 copy
// ===========================================================================
__global__ __launch_bounds__(256) void to_half(
    const float* __restrict__ x, __half* __restrict__ xh)
{
    const int i = (blockIdx.x * 256 + threadIdx.x) * 4;
    float4 v = *(const float4*)&x[i];
    *(__half2*)&xh[i]     = __floats2half2_rn(v.x, v.y);
    *(__half2*)&xh[i + 2] = __floats2half2_rn(v.z, v.w);
}

// ===========================================================================
// Weight transpose -> fp16: Wt[n][k] = W[k][n]
// ===========================================================================
__global__ __launch_bounds__(256) void transpose_w(
    const float* __restrict__ Wq, const float* __restrict__ Wk,
    const float* __restrict__ Wv, const float* __restrict__ Wo,
    __half* __restrict__ Wt, __half* __restrict__ WtO)
{
    __shared__ float t[32][33];
    const int z = blockIdx.z;
    const float* W = (z == 0) ? Wq : (z == 1) ? Wk : (z == 2) ? Wv : Wo;
    __half* O = (z == 3) ? WtO : (Wt + z * Emb * Cin);
    const int tx = threadIdx.x & 31, ty = threadIdx.x >> 5;
    const int k0 = blockIdx.y * 32, n0 = blockIdx.x * 32;
#pragma unroll
    for (int i = 0; i < 4; i++)
        t[ty + i * 8][tx] = W[(k0 + ty + i * 8) * 512 + n0 + tx];
    __syncthreads();
#pragma unroll
    for (int i = 0; i < 4; i++)
        O[(n0 + ty + i * 8) * 512 + k0 + tx] = __float2half(t[tx][ty + i * 8]);
}

// ===========================================================================
// Pt[128][128] fp16: rows 0-62 = pos_emb_w^T, rows 64-126 = pos_emb_h^T
// ===========================================================================
__global__ __launch_bounds__(256) void build_pt(
    const float* __restrict__ pw, const float* __restrict__ ph,
    __half* __restrict__ Pt)
{
    const int idx = blockIdx.x * 256 + threadIdx.x;
    const int r = idx >> 7, d = idx & 127;
    float v = 0.f;
    if (r < 63)                  v = pw[d * 63 + r];
    else if (r >= 64 && r < 127) v = ph[d * 63 + (r - 64)];
    Pt[idx] = __float2half(v);
}

// ===========================================================================
// V transpose: Vth[b][h][d][key] = Vh[b*1024+key][h*128+d]
// ===========================================================================
__global__ __launch_bounds__(256) void vtrans_h(
    const __half* __restrict__ V, __half* __restrict__ Vt)
{
    __shared__ __half t[32][33];
    const int bh = blockIdx.z;
    const int b = bh >> 2, h = bh & 3;
    const int k0 = blockIdx.x * 32, d0 = blockIdx.y * 32;
    const int tx = threadIdx.x & 31, ty = threadIdx.x >> 5;
#pragma unroll
    for (int i = 0; i < 4; i++)
        t[ty + i * 8][tx] = V[(b * Lq + k0 + ty + i * 8) * Emb + h * KDim + d0 + tx];
    __syncthreads();
#pragma unroll
    for (int i = 0; i < 4; i++)
        Vt[(bh * KDim + d0 + ty + i * 8) * Lq + k0 + tx] = t[tx][ty + i * 8];
}

// ===========================================================================
// fp16 mma GEMM: C = alpha * A[M,512] @ Bt[N,512]^T
// CTA 128x128, 8 warps (32x64), K-chunk 64, 2-stage cp.async, ldmatrix.
// Output fp16 (C0/C1/C2 by outi) or fp32 (Cf if non-null).
// ===========================================================================
#define GH_A_HALVES (128 * 72)
#define GH_STAGE_HALVES (2 * GH_A_HALVES)
#define GH_SMEM_BYTES (2 * GH_STAGE_HALVES * 2)   // 73728

__global__ __launch_bounds__(256, 2) void gemm_h(
    const __half* __restrict__ A, const __half* __restrict__ Bt,
    __half* __restrict__ C0, __half* __restrict__ C1, __half* __restrict__ C2,
    float* __restrict__ Cf, float alpha0)
{
    extern __shared__ __half smh[];
    const uint32_t sb = smem_u32(smh);
    const int tid = threadIdx.x, lane = tid & 31, wid = tid >> 5;
    const int warp_m = wid & 3, warp_n = wid >> 2;
    const int gid = lane >> 2, tig = lane & 3;

    const int bx = blockIdx.x, outi = bx >> 2;
    __half* Ch = (outi == 0) ? C0 : (outi == 1) ? C1 : C2;
    const float alpha = (outi == 0) ? alpha0 : 1.0f;
    const int m0 = blockIdx.y * 128;
    const int nrow0 = bx * 128;
    const int ncol0 = (bx & 3) * 128;

    const __half* Ab = A + m0 * 512;
    const __half* Bb = Bt + nrow0 * 512;

    float c[2][8][4];
#pragma unroll
    for (int mf = 0; mf < 2; mf++)
#pragma unroll
        for (int nf = 0; nf < 8; nf++)
#pragma unroll
            for (int e = 0; e < 4; e++) c[mf][nf][e] = 0.f;

    auto issue = [&](int kc, int s) {
#pragma unroll
        for (int it = 0; it < 4; it++) {
            const int idx = it * 256 + tid;      // 0..1023
            const int row = idx >> 3, c8 = idx & 7;
            const uint32_t dA = sb + (s * GH_STAGE_HALVES + row * 72 + c8 * 8) * 2;
            CP_ASYNC16(dA, Ab + row * 512 + kc * 64 + c8 * 8);
            CP_ASYNC16(dA + GH_A_HALVES * 2, Bb + row * 512 + kc * 64 + c8 * 8);
        }
        CP_COMMIT();
    };

    issue(0, 0);

    // lane-derived ldsm offsets
    const int a_r = lane & 15, a_c = (lane >> 4) << 3;
    const int b_r = ((lane >> 4) << 3) + (lane & 7), b_c = ((lane >> 3) & 1) << 3;

    for (int kc = 0; kc < 8; kc++) {
        const int s = kc & 1;
        if (kc < 7) { issue(kc + 1, s ^ 1); CP_WAIT1(); }
        else        { CP_WAIT0(); }
        __syncthreads();

        const uint32_t sA = sb + s * GH_STAGE_HALVES * 2;
        const uint32_t sB = sA + GH_A_HALVES * 2;

#pragma unroll
        for (int t = 0; t < 4; t++) {
            const int kb = t * 16;
            uint32_t a[2][4];
#pragma unroll
            for (int mf = 0; mf < 2; mf++) {
                const uint32_t ad = sA +
                    ((warp_m * 32 + mf * 16 + a_r) * 72 + kb + a_c) * 2;
                LDSM_X4(a[mf][0], a[mf][1], a[mf][2], a[mf][3], ad);
            }
#pragma unroll
            for (int nf2 = 0; nf2 < 4; nf2++) {
                const uint32_t bd = sB +
                    ((warp_n * 64 + nf2 * 16 + b_r) * 72 + kb + b_c) * 2;
                uint32_t b0, b1, b2, b3;
                LDSM_X4(b0, b1, b2, b3, bd);
#pragma unroll
                for (int mf = 0; mf < 2; mf++) {
                    mma_f16(c[mf][nf2 * 2],     a[mf], b0, b1);
                    mma_f16(c[mf][nf2 * 2 + 1], a[mf], b2, b3);
                }
            }
        }
        __syncthreads();
    }

#pragma unroll
    for (int mf = 0; mf < 2; mf++) {
        const int row = m0 + warp_m * 32 + mf * 16 + gid;
#pragma unroll
        for (int nf = 0; nf < 8; nf++) {
            const int col = ncol0 + warp_n * 64 + nf * 8 + tig * 2;
            float v0 = c[mf][nf][0] * alpha, v1 = c[mf][nf][1] * alpha;
            float v2 = c[mf][nf][2] * alpha, v3 = c[mf][nf][3] * alpha;
            if (Cf) {
                *(float2*)(Cf + row * 512 + col)       = make_float2(v0, v1);
                *(float2*)(Cf + (row + 8) * 512 + col) = make_float2(v2, v3);
            } else {
                *(__half2*)(Ch + row * 512 + col)       = __floats2half2_rn(v0, v1);
                *(__half2*)(Ch + (row + 8) * 512 + col) = __floats2half2_rn(v2, v3);
            }
        }
    }
}

// ===========================================================================
// relpos fp16 mma: Qflat[32768,128] @ Pt[128,128]^T -> RW|RH fp32
// CTA 128x128, single-shot K=128, ldmatrix, stride 136.
// ===========================================================================
#define RP_A_HALVES (128 * 136)
#define RP_SMEM_BYTES (2 * RP_A_HALVES * 2)     // 69632

__global__ __launch_bounds__(256) void relpos_h(
    const __half* __restrict__ Q, const __half* __restrict__ Pt,
    float* __restrict__ RW, float* __restrict__ RH)
{
    extern __shared__ __half smh[];
    const uint32_t sb = smem_u32(smh);
    const int tid = threadIdx.x, lane = tid & 31, wid = tid >> 5;
    const int warp_m = wid & 3, warp_n = wid >> 2;
    const int gid = lane >> 2, tig = lane & 3;
    const int m0 = blockIdx.x * 128;

#pragma unroll
    for (int it = 0; it < 8; it++) {
        const int idx = it * 256 + tid;          // 0..2047
        const int row = idx >> 4, c8 = idx & 15;
        CP_ASYNC16(sb + (row * 136 + c8 * 8) * 2,
                   Q + (m0 + row) * 128 + c8 * 8);
        CP_ASYNC16(sb + (RP_A_HALVES + row * 136 + c8 * 8) * 2,
                   Pt + row * 128 + c8 * 8);
    }
    CP_COMMIT();
    CP_WAIT0();
    __syncthreads();

    float c[2][8][4];
#pragma unroll
    for (int mf = 0; mf < 2; mf++)
#pragma unroll
        for (int nf = 0; nf < 8; nf++)
#pragma unroll
            for (int e = 0; e < 4; e++) c[mf][nf][e] = 0.f;

    const int a_r = lane & 15, a_c = (lane >> 4) << 3;
    const int b_r = ((lane >> 4) << 3) + (lane & 7), b_c = ((lane >> 3) & 1) << 3;
    const uint32_t sB = sb + RP_A_HALVES * 2;

#pragma unroll
    for (int t = 0; t < 8; t++) {
        const int kb = t * 16;
        uint32_t a[2][4];
#pragma unroll
        for (int mf = 0; mf < 2; mf++) {
            const uint32_t ad = sb +
                ((warp_m * 32 + mf * 16 + a_r) * 136 + kb + a_c) * 2;
            LDSM_X4(a[mf][0], a[mf][1], a[mf][2], a[mf][3], ad);
        }
#pragma unroll
        for (int nf2 = 0; nf2 < 4; nf2++) {
            const uint32_t bd = sB +
                ((warp_n * 64 + nf2 * 16 + b_r) * 136 + kb + b_c) * 2;
            uint32_t b0, b1, b2, b3;
            LDSM_X4(b0, b1, b2, b3, bd);
#pragma unroll
            for (int mf = 0; mf < 2; mf++) {
                mma_f16(c[mf][nf2 * 2],     a[mf], b0, b1);
                mma_f16(c[mf][nf2 * 2 + 1], a[mf], b2, b3);
            }
        }
    }

    auto put = [&](int row, int col, float v) {
        if (col < 63)                    RW[row * 64 + col] = v;
        else if (col >= 64 && col < 127) RH[row * 64 + col - 64] = v;
    };
#pragma unroll
    for (int mf = 0; mf < 2; mf++) {
        const int row = m0 + warp_m * 32 + mf * 16 + gid;
#pragma unroll
        for (int nf = 0; nf < 8; nf++) {
            const int col = warp_n * 64 + nf * 8 + tig * 2;
            put(row,     col,     c[mf][nf][0]);
            put(row,     col + 1, c[mf][nf][1]);
            put(row + 8, col,     c[mf][nf][2]);
            put(row + 8, col + 1, c[mf][nf][3]);
        }
    }
}

// ===========================================================================
// Flash attention fp16: ldmatrix + m16n8k16, register softmax, double-buffer.
// smem (halves): Ks[2][64*136], Vs[2][128*72], Ps[128*72]; RHs fp32 [128*64].
// ===========================================================================
#define AH_KS   0
#define AH_KST  8704
#define AH_VS   17408
#define AH_VST  9216
#define AH_PS   35840
#define AH_RHS_BYTES 90112
#define AH_SMEM 122880

__global__ __launch_bounds__(256, 1) void attn_h(
    const __half* __restrict__ Qh, const __half* __restrict__ Kh,
    const __half* __restrict__ Vth, const float* __restrict__ RW,
    const float* __restrict__ RH, __half* __restrict__ AOh)
{
    extern __shared__ char smc[];
    float* RHs = (float*)(smc + AH_RHS_BYTES);
    const uint32_t sb = smem_u32(smc);

    const int tid = threadIdx.x, lane = tid & 31, wm = tid >> 5;
    const int gid = lane >> 2, tig = lane & 3;
    const int m0 = blockIdx.x * 128, h = blockIdx.y, b = blockIdx.z;

    // RH rows -> smem (fp32)
    for (int i4 = tid; i4 < 128 * 16; i4 += 256) {
        int r = i4 >> 4, c4 = i4 & 15;
        *(float4*)&RHs[r * 64 + c4 * 4] =
            *(const float4*)&RH[((b * Lq + m0 + r) * NHd + h) * 64 + c4 * 4];
    }

    // RW bias registers (iter-invariant gather from global)
    const int row0 = wm * 16 + gid;
    float rwv[2][16];
#pragma unroll
    for (int i = 0; i < 2; i++) {
        const int r = row0 + 8 * i;
        const float* RWr = RW + ((b * Lq + m0 + r) * NHd + h) * 64 - (r & 31) + 31;
#pragma unroll
        for (int nf = 0; nf < 8; nf++) {
            rwv[i][nf * 2]     = RWr[((nf * 8 + 2 * tig) & 31)];
            rwv[i][nf * 2 + 1] = RWr[((nf * 8 + 2 * tig + 1) & 31)];
        }
    }
    const int ymr0 = (m0 + row0) >> 5;
    const int ymr1 = (m0 + row0 + 8) >> 5;

    // Q fragments (fp16 half2 = one b32 each), resident
    const __half* Qg = Qh + (b * Lq + m0 + wm * 16) * Emb + h * KDim;
    uint32_t qf[8][4];
#pragma unroll
    for (int k16 = 0; k16 < 8; k16++) {
        qf[k16][0] = *(const uint32_t*)(Qg + gid * 512 + k16 * 16 + 2 * tig);
        qf[k16][1] = *(const uint32_t*)(Qg + (gid + 8) * 512 + k16 * 16 + 2 * tig);
        qf[k16][2] = *(const uint32_t*)(Qg + gid * 512 + k16 * 16 + 2 * tig + 8);
        qf[k16][3] = *(const uint32_t*)(Qg + (gid + 8) * 512 + k16 * 16 + 2 * tig + 8);
    }

    float acc[16][4];
#pragma unroll
    for (int n2 = 0; n2 < 16; n2++)
#pragma unroll
        for (int e = 0; e < 4; e++) acc[n2][e] = 0.f;
    float mrow[2] = {-3.0e38f, -3.0e38f};
    float lrow[2] = {0.f, 0.f};

    const __half* Kbase = Kh + (b * Lq) * Emb + h * KDim;
    const __half* Vbase = Vth + (b * NHd + h) * KDim * Lq;

    auto load_tile = [&](int n0, int st) {
#pragma unroll
        for (int it = 0; it < 4; it++) {
            const int idx = it * 256 + tid;      // 0..1023
            const int key = idx >> 4, c8 = idx & 15;
            CP_ASYNC16(sb + (AH_KS + st * AH_KST + key * 136 + c8 * 8) * 2,
                       Kbase + (n0 + key) * 512 + c8 * 8);
        }
#pragma unroll
        for (int it = 0; it < 4; it++) {
            const int idx = it * 256 + tid;
            const int d = idx >> 3, c8 = idx & 7;
            CP_ASYNC16(sb + (AH_VS + st * AH_VST + d * 72 + c8 * 8) * 2,
                       Vbase + d * Lq + n0 + c8 * 8);
        }
        CP_COMMIT();
    };

    load_tile(0, 0);

    const int b_r = ((lane >> 4) << 3) + (lane & 7), b_c = ((lane >> 3) & 1) << 3;
    const int a_r = lane & 15, a_c = (lane >> 4) << 3;

    for (int it = 0; it < 16; it++) {
        const int n0 = it * 64;
        const int st = it & 1;
        if (it < 15) { load_tile(n0 + 64, st ^ 1); CP_WAIT1(); }
        else         { CP_WAIT0(); }
        __syncthreads();

        const uint32_t sK = sb + (AH_KS + st * AH_KST) * 2;
        const uint32_t sV = sb + (AH_VS + st * AH_VST) * 2;

        // S = Q K^T
        float s[8][4];
#pragma unroll
        for (int nf = 0; nf < 8; nf++)
#pragma unroll
            for (int e = 0; e < 4; e++) s[nf][e] = 0.f;
#pragma unroll
        for (int k16 = 0; k16 < 8; k16++) {
#pragma unroll
            for (int nf2 = 0; nf2 < 4; nf2++) {
                const uint32_t bd = sK +
                    ((nf2 * 16 + b_r) * 136 + k16 * 16 + b_c) * 2;
                uint32_t b0, b1, b2, b3;
                LDSM_X4(b0, b1, b2, b3, bd);
                mma_f16(s[nf2 * 2],     qf[k16], b0, b1);
                mma_f16(s[nf2 * 2 + 1], qf[k16], b2, b3);
            }
        }

        // bias
        const int seg = n0 >> 5;
        float rh[2][2];
        rh[0][0] = RHs[row0 * 64 + seg - ymr0 + 31];
        rh[0][1] = RHs[row0 * 64 + seg + 1 - ymr0 + 31];
        rh[1][0] = RHs[(row0 + 8) * 64 + seg - ymr1 + 31];
        rh[1][1] = RHs[(row0 + 8) * 64 + seg + 1 - ymr1 + 31];
#pragma unroll
        for (int nf = 0; nf < 8; nf++) {
            const int u = nf >> 2;
            s[nf][0] += rwv[0][nf * 2]     + rh[0][u];
            s[nf][1] += rwv[0][nf * 2 + 1] + rh[0][u];
            s[nf][2] += rwv[1][nf * 2]     + rh[1][u];
            s[nf][3] += rwv[1][nf * 2 + 1] + rh[1][u];
        }

        // online softmax (register resident)
#pragma unroll
        for (int i = 0; i < 2; i++) {
            float mx = s[0][2 * i];
#pragma unroll
            for (int nf = 0; nf < 8; nf++) {
                mx = fmaxf(mx, s[nf][2 * i]);
                mx = fmaxf(mx, s[nf][2 * i + 1]);
            }
            mx = fmaxf(mx, __shfl_xor_sync(0xffffffffu, mx, 1));
            mx = fmaxf(mx, __shfl_xor_sync(0xffffffffu, mx, 2));
            const float mnew = fmaxf(mrow[i], mx);
            const float fsc = fexp2((mrow[i] - mnew) * L2E);
            mrow[i] = mnew;
            float sum = 0.f;
#pragma unroll
            for (int nf = 0; nf < 8; nf++) {
                float p0 = fexp2((s[nf][2 * i] - mnew) * L2E);
                float p1 = fexp2((s[nf][2 * i + 1] - mnew) * L2E);
                sum += p0 + p1;
                s[nf][2 * i] = p0;
                s[nf][2 * i + 1] = p1;
            }
            sum += __shfl_xor_sync(0xffffffffu, sum, 1);
            sum += __shfl_xor_sync(0xffffffffu, sum, 2);
            lrow[i] = lrow[i] * fsc + sum;
#pragma unroll
            for (int n2 = 0; n2 < 16; n2++) {
                acc[n2][2 * i]     *= fsc;
                acc[n2][2 * i + 1] *= fsc;
            }
        }

        // P -> smem fp16 (warp-private rows)
        {
            __half* Ps = (__half*)smc + AH_PS;
#pragma unroll
            for (int nf = 0; nf < 8; nf++) {
                *(__half2*)(Ps + row0 * 72 + nf * 8 + 2 * tig) =
                    __floats2half2_rn(s[nf][0], s[nf][1]);
                *(__half2*)(Ps + (row0 + 8) * 72 + nf * 8 + 2 * tig) =
                    __floats2half2_rn(s[nf][2], s[nf][3]);
            }
        }
        __syncwarp();

        // acc += P @ V
#pragma unroll
        for (int kk = 0; kk < 4; kk++) {
            const uint32_t pd = sb +
                (AH_PS + (wm * 16 + a_r) * 72 + kk * 16 + a_c) * 2;
            uint32_t pa[4];
            LDSM_X4(pa[0], pa[1], pa[2], pa[3], pd);
#pragma unroll
            for (int nf2 = 0; nf2 < 8; nf2++) {
                const uint32_t bd = sV +
                    ((nf2 * 16 + b_r) * 72 + kk * 16 + b_c) * 2;
                uint32_t b0, b1, b2, b3;
                LDSM_X4(b0, b1, b2, b3, bd);
                mma_f16(acc[nf2 * 2],     pa, b0, b1);
                mma_f16(acc[nf2 * 2 + 1], pa, b2, b3);
            }
        }
        __syncthreads();
    }

    // epilogue -> AOh fp16
    const float inv0 = 1.f / lrow[0];
    const float inv1 = 1.f / lrow[1];
    const int gm0 = b * Lq + m0 + wm * 16 + gid;
#pragma unroll
    for (int n2 = 0; n2 < 16; n2++) {
        const int col = n2 * 8 + 2 * tig;
        *(__half2*)(AOh + (gm0 * NHd + h) * KDim + col) =
            __floats2half2_rn(acc[n2][0] * inv0, acc[n2][1] * inv0);
        *(__half2*)(AOh + ((gm0 + 8) * NHd + h) * KDim + col) =
            __floats2half2_rn(acc[n2][2] * inv1, acc[n2][3] * inv1);
    }
}

// ---------------------------------------------------------------------------
extern "C" void kernel_launch(void* const* d_in, const int* in_sizes, int n_in,
                              void* d_out, int out_size)
{
    (void)in_sizes; (void)n_in; (void)out_size;
    const float* x  = (const float*)d_in[0];
    const float* Wq = (const float*)d_in[1];
    const float* Wk = (const float*)d_in[2];
    const float* Wv = (const float*)d_in[3];
    const float* Wo = (const float*)d_in[4];
    const float* pw = (const float*)d_in[5];
    const float* ph = (const float*)d_in[6];
    float* out = (float*)d_out;

    __half *xh, *qh, *kh, *vh, *vth, *aoh, *wth, *wtoh, *pth;
    float *rw, *rh;
    cudaGetSymbolAddress((void**)&xh,   g_Xh);
    cudaGetSymbolAddress((void**)&qh,   g_Qh);
    cudaGetSymbolAddress((void**)&kh,   g_Kh);
    cudaGetSymbolAddress((void**)&vh,   g_Vh);
    cudaGetSymbolAddress((void**)&vth,  g_Vth);
    cudaGetSymbolAddress((void**)&aoh,  g_AOh);
    cudaGetSymbolAddress((void**)&wth,  g_Wth);
    cudaGetSymbolAddress((void**)&wtoh, g_WtOh);
    cudaGetSymbolAddress((void**)&pth,  g_Pth);
    cudaGetSymbolAddress((void**)&rw,   g_RW);
    cudaGetSymbolAddress((void**)&rh,   g_RH);

    const float scale = 0.08838834764831845f;  // 1/sqrt(128)

    cudaFuncSetAttribute(gemm_h,
                         cudaFuncAttributeMaxDynamicSharedMemorySize,
                         GH_SMEM_BYTES);
    cudaFuncSetAttribute(relpos_h,
                         cudaFuncAttributeMaxDynamicSharedMemorySize,
                         RP_SMEM_BYTES);
    cudaFuncSetAttribute(attn_h,
                         cudaFuncAttributeMaxDynamicSharedMemorySize,
                         AH_SMEM);

    transpose_w<<<dim3(16, 16, 4), 256>>>(Wq, Wk, Wv, Wo, wth, wtoh);
    build_pt<<<64, 256>>>(pw, ph, pth);
    to_half<<<4096, 256>>>(x, xh);

    // QKV: grid.x 0..11 -> (Q|K|V) x 4 col-tiles
    gemm_h<<<dim3(12, 64), 256, GH_SMEM_BYTES>>>(
        xh, wth, qh, kh, vh, nullptr, scale);

    vtrans_h<<<dim3(32, 4, 32), 256>>>(vh, vth);

    relpos_h<<<256, 256, RP_SMEM_BYTES>>>(qh, pth, rw, rh);

    attn_h<<<dim3(8, NHd, Bz), 256, AH_SMEM>>>(qh, kh, vth, rw, rh, aoh);

    // Output projection (fp32 out)
    gemm_h<<<dim3(4, 64), 256, GH_SMEM_BYTES>>>(
        aoh, wtoh, nullptr, nullptr, nullptr, out, 1.0f);
}

// round 8
// speedup vs baseline: 7.8336x; 1.0530x over previous
#include <cuda_runtime.h>
#include <cuda_fp16.h>
#include <cstdint>

// Problem constants
#define Bz    8
#define HHg   32
#define WWg   32
#define Lq    1024          // HHg*WWg
#define Cin   512
#define NHd   4
#define KDim  128
#define Emb   512           // NHd*KDim
#define Mrows 8192          // Bz*Lq

// Scratch (device globals: allocation-free rule)
__device__ __half g_Xh  [Mrows * Cin];
__device__ __half g_Qh  [Mrows * Emb];
__device__ __half g_Kh  [Mrows * Emb];
__device__ __half g_Vh  [Mrows * Emb];
__device__ __half g_Vth [Bz * NHd * KDim * Lq];  // [b][h][d][key]
__device__ __half g_AOh [Mrows * Emb];
__device__ float  g_RW  [Mrows * NHd * 64];      // 63 used, padded
__device__ float  g_RH  [Mrows * NHd * 64];
__device__ __half g_Wth [3 * Emb * Cin];         // transposed Wq|Wk|Wv [1536][512]
__device__ __half g_WtOh[Emb * Emb];             // transposed Wo [512][512]
__device__ __half g_Pth [128 * 128];             // padded pos tables [r][d]

// ===========================================================================
// Helpers
// ===========================================================================
__device__ __forceinline__ uint32_t smem_u32(const void* p) {
    uint32_t a;
    asm("{ .reg .u64 t; cvta.to.shared.u64 t, %1; cvt.u32.u64 %0, t; }"
        : "=r"(a) : "l"(p));
    return a;
}
#define CP_ASYNC16(dst, src) \
    asm volatile("cp.async.cg.shared.global [%0], [%1], 16;" \
                 :: "r"(dst), "l"(src) : "memory")
#define CP_COMMIT() asm volatile("cp.async.commit_group;" ::: "memory")
#define CP_WAIT2()  asm volatile("cp.async.wait_group 2;" ::: "memory")
#define CP_WAIT1()  asm volatile("cp.async.wait_group 1;" ::: "memory")
#define CP_WAIT0()  asm volatile("cp.async.wait_group 0;" ::: "memory")

#define LDSM_X4(r0, r1, r2, r3, addr) \
    asm volatile("ldmatrix.sync.aligned.m8n8.x4.shared.b16 {%0,%1,%2,%3}, [%4];" \
        : "=r"(r0), "=r"(r1), "=r"(r2), "=r"(r3) : "r"(addr))

__device__ __forceinline__ void mma_f16(float* c, const uint32_t* a,
                                        uint32_t b0, uint32_t b1) {
    asm volatile(
        "mma.sync.aligned.m16n8k16.row.col.f32.f16.f16.f32 "
        "{%0,%1,%2,%3}, {%4,%5,%6,%7}, {%8,%9}, {%0,%1,%2,%3};"
        : "+f"(c[0]), "+f"(c[1]), "+f"(c[2]), "+f"(c[3])
        : "r"(a[0]), "r"(a[1]), "r"(a[2]), "r"(a[3]), "r"(b0), "r"(b1));
}
__device__ __forceinline__ uint32_t packh2(float a, float b) {
    __half2 h = __floats2half2_rn(a, b);
    return *(uint32_t*)&h;
}

// Fast exp2 on the FMA pipe
__device__ __forceinline__ float fexp2(float x) {
    x = fmaxf(x, -120.f);
    float r = rintf(x);
    float f = x - r;
    float p =              0.0013333558f;
    p = fmaf(p, f, 0.0096181291f);
    p = fmaf(p, f, 0.0555041087f);
    p = fmaf(p, f, 0.2402265069f);
    p = fmaf(p, f, 0.6931471806f);
    p = fmaf(p, f, 1.0f);
    int e = (int)r;
    return p * __int_as_float((e + 127) << 23);
}
#define L2E 1.4426950408889634f

// ===========================================================================
// x -> fp16 copy
// ===========================================================================
__global__ __launch_bounds__(256) void to_half(
    const float* __restrict__ x, __half* __restrict__ xh)
{
    const int i = (blockIdx.x * 256 + threadIdx.x) * 4;
    float4 v = *(const float4*)&x[i];
    *(__half2*)&xh[i]     = __floats2half2_rn(v.x, v.y);
    *(__half2*)&xh[i + 2] = __floats2half2_rn(v.z, v.w);
}

// ===========================================================================
// Weight transpose -> fp16: Wt[n][k] = W[k][n]
// ===========================================================================
__global__ __launch_bounds__(256) void transpose_w(
    const float* __restrict__ Wq, const float* __restrict__ Wk,
    const float* __restrict__ Wv, const float* __restrict__ Wo,
    __half* __restrict__ Wt, __half* __restrict__ WtO)
{
    __shared__ float t[32][33];
    const int z = blockIdx.z;
    const float* W = (z == 0) ? Wq : (z == 1) ? Wk : (z == 2) ? Wv : Wo;
    __half* O = (z == 3) ? WtO : (Wt + z * Emb * Cin);
    const int tx = threadIdx.x & 31, ty = threadIdx.x >> 5;
    const int k0 = blockIdx.y * 32, n0 = blockIdx.x * 32;
#pragma unroll
    for (int i = 0; i < 4; i++)
        t[ty + i * 8][tx] = W[(k0 + ty + i * 8) * 512 + n0 + tx];
    __syncthreads();
#pragma unroll
    for (int i = 0; i < 4; i++)
        O[(n0 + ty + i * 8) * 512 + k0 + tx] = __float2half(t[tx][ty + i * 8]);
}

// ===========================================================================
// Pt[128][128] fp16: rows 0-62 = pos_emb_w^T, rows 64-126 = pos_emb_h^T
// ===========================================================================
__global__ __launch_bounds__(256) void build_pt(
    const float* __restrict__ pw, const float* __restrict__ ph,
    __half* __restrict__ Pt)
{
    const int idx = blockIdx.x * 256 + threadIdx.x;
    const int r = idx >> 7, d = idx & 127;
    float v = 0.f;
    if (r < 63)                  v = pw[d * 63 + r];
    else if (r >= 64 && r < 127) v = ph[d * 63 + (r - 64)];
    Pt[idx] = __float2half(v);
}

// ===========================================================================
// V transpose: Vth[b][h][d][key] = Vh[b*1024+key][h*128+d]
// ===========================================================================
__global__ __launch_bounds__(256) void vtrans_h(
    const __half* __restrict__ V, __half* __restrict__ Vt)
{
    __shared__ __half t[32][33];
    const int bh = blockIdx.z;
    const int b = bh >> 2, h = bh & 3;
    const int k0 = blockIdx.x * 32, d0 = blockIdx.y * 32;
    const int tx = threadIdx.x & 31, ty = threadIdx.x >> 5;
#pragma unroll
    for (int i = 0; i < 4; i++)
        t[ty + i * 8][tx] = V[(b * Lq + k0 + ty + i * 8) * Emb + h * KDim + d0 + tx];
    __syncthreads();
#pragma unroll
    for (int i = 0; i < 4; i++)
        Vt[(bh * KDim + d0 + ty + i * 8) * Lq + k0 + tx] = t[tx][ty + i * 8];
}

// ===========================================================================
// fp16 mma GEMM: C = alpha * A[M,512] @ Bt[N,512]^T
// CTA 128x128, 8 warps (32x64), K-chunk 64, 3-stage cp.async, ldmatrix.
// ===========================================================================
#define GH_A_HALVES (128 * 72)
#define GH_STAGE_HALVES (2 * GH_A_HALVES)
#define GH_SMEM_BYTES (3 * GH_STAGE_HALVES * 2)   // 110592

__global__ __launch_bounds__(256, 2) void gemm_h(
    const __half* __restrict__ A, const __half* __restrict__ Bt,
    __half* __restrict__ C0, __half* __restrict__ C1, __half* __restrict__ C2,
    float* __restrict__ Cf, float alpha0)
{
    extern __shared__ __half smh[];
    const uint32_t sb = smem_u32(smh);
    const int tid = threadIdx.x, lane = tid & 31, wid = tid >> 5;
    const int warp_m = wid & 3, warp_n = wid >> 2;
    const int gid = lane >> 2, tig = lane & 3;

    const int bx = blockIdx.x, outi = bx >> 2;
    __half* Ch = (outi == 0) ? C0 : (outi == 1) ? C1 : C2;
    const float alpha = (outi == 0) ? alpha0 : 1.0f;
    const int m0 = blockIdx.y * 128;
    const int nrow0 = bx * 128;
    const int ncol0 = (bx & 3) * 128;

    const __half* Ab = A + m0 * 512;
    const __half* Bb = Bt + nrow0 * 512;

    float c[2][8][4];
#pragma unroll
    for (int mf = 0; mf < 2; mf++)
#pragma unroll
        for (int nf = 0; nf < 8; nf++)
#pragma unroll
            for (int e = 0; e < 4; e++) c[mf][nf][e] = 0.f;

    auto issue = [&](int kc, int s) {
#pragma unroll
        for (int it = 0; it < 4; it++) {
            const int idx = it * 256 + tid;
            const int row = idx >> 3, c8 = idx & 7;
            const uint32_t dA = sb + (s * GH_STAGE_HALVES + row * 72 + c8 * 8) * 2;
            CP_ASYNC16(dA, Ab + row * 512 + kc * 64 + c8 * 8);
            CP_ASYNC16(dA + GH_A_HALVES * 2, Bb + row * 512 + kc * 64 + c8 * 8);
        }
        CP_COMMIT();
    };

    issue(0, 0);
    issue(1, 1);

    const int a_r = lane & 15, a_c = (lane >> 4) << 3;
    const int b_r = ((lane >> 4) << 3) + (lane & 7), b_c = ((lane >> 3) & 1) << 3;

    int s = 0;
    for (int kc = 0; kc < 8; kc++) {
        if (kc < 6)      { issue(kc + 2, (kc + 2) % 3); CP_WAIT2(); }
        else if (kc == 6) { CP_WAIT1(); }
        else             { CP_WAIT0(); }
        __syncthreads();

        const uint32_t sA = sb + s * GH_STAGE_HALVES * 2;
        const uint32_t sB = sA + GH_A_HALVES * 2;

#pragma unroll
        for (int t = 0; t < 4; t++) {
            const int kb = t * 16;
            uint32_t a[2][4];
#pragma unroll
            for (int mf = 0; mf < 2; mf++) {
                const uint32_t ad = sA +
                    ((warp_m * 32 + mf * 16 + a_r) * 72 + kb + a_c) * 2;
                LDSM_X4(a[mf][0], a[mf][1], a[mf][2], a[mf][3], ad);
            }
#pragma unroll
            for (int nf2 = 0; nf2 < 4; nf2++) {
                const uint32_t bd = sB +
                    ((warp_n * 64 + nf2 * 16 + b_r) * 72 + kb + b_c) * 2;
                uint32_t b0, b1, b2, b3;
                LDSM_X4(b0, b1, b2, b3, bd);
#pragma unroll
                for (int mf = 0; mf < 2; mf++) {
                    mma_f16(c[mf][nf2 * 2],     a[mf], b0, b1);
                    mma_f16(c[mf][nf2 * 2 + 1], a[mf], b2, b3);
                }
            }
        }
        __syncthreads();
        s = (s + 1) % 3;
    }

#pragma unroll
    for (int mf = 0; mf < 2; mf++) {
        const int row = m0 + warp_m * 32 + mf * 16 + gid;
#pragma unroll
        for (int nf = 0; nf < 8; nf++) {
            const int col = ncol0 + warp_n * 64 + nf * 8 + tig * 2;
            float v0 = c[mf][nf][0] * alpha, v1 = c[mf][nf][1] * alpha;
            float v2 = c[mf][nf][2] * alpha, v3 = c[mf][nf][3] * alpha;
            if (Cf) {
                *(float2*)(Cf + row * 512 + col)       = make_float2(v0, v1);
                *(float2*)(Cf + (row + 8) * 512 + col) = make_float2(v2, v3);
            } else {
                *(__half2*)(Ch + row * 512 + col)       = __floats2half2_rn(v0, v1);
                *(__half2*)(Ch + (row + 8) * 512 + col) = __floats2half2_rn(v2, v3);
            }
        }
    }
}

// ===========================================================================
// relpos fp16 mma: Qflat[32768,128] @ Pt[128,128]^T -> RW|RH fp32
// ===========================================================================
#define RP_A_HALVES (128 * 136)
#define RP_SMEM_BYTES (2 * RP_A_HALVES * 2)     // 69632

__global__ __launch_bounds__(256) void relpos_h(
    const __half* __restrict__ Q, const __half* __restrict__ Pt,
    float* __restrict__ RW, float* __restrict__ RH)
{
    extern __shared__ __half smh[];
    const uint32_t sb = smem_u32(smh);
    const int tid = threadIdx.x, lane = tid & 31, wid = tid >> 5;
    const int warp_m = wid & 3, warp_n = wid >> 2;
    const int gid = lane >> 2, tig = lane & 3;
    const int m0 = blockIdx.x * 128;

#pragma unroll
    for (int it = 0; it < 8; it++) {
        const int idx = it * 256 + tid;
        const int row = idx >> 4, c8 = idx & 15;
        CP_ASYNC16(sb + (row * 136 + c8 * 8) * 2,
                   Q + (m0 + row) * 128 + c8 * 8);
        CP_ASYNC16(sb + (RP_A_HALVES + row * 136 + c8 * 8) * 2,
                   Pt + row * 128 + c8 * 8);
    }
    CP_COMMIT();
    CP_WAIT0();
    __syncthreads();

    float c[2][8][4];
#pragma unroll
    for (int mf = 0; mf < 2; mf++)
#pragma unroll
        for (int nf = 0; nf < 8; nf++)
#pragma unroll
            for (int e = 0; e < 4; e++) c[mf][nf][e] = 0.f;

    const int a_r = lane & 15, a_c = (lane >> 4) << 3;
    const int b_r = ((lane >> 4) << 3) + (lane & 7), b_c = ((lane >> 3) & 1) << 3;
    const uint32_t sB = sb + RP_A_HALVES * 2;

#pragma unroll
    for (int t = 0; t < 8; t++) {
        const int kb = t * 16;
        uint32_t a[2][4];
#pragma unroll
        for (int mf = 0; mf < 2; mf++) {
            const uint32_t ad = sb +
                ((warp_m * 32 + mf * 16 + a_r) * 136 + kb + a_c) * 2;
            LDSM_X4(a[mf][0], a[mf][1], a[mf][2], a[mf][3], ad);
        }
#pragma unroll
        for (int nf2 = 0; nf2 < 4; nf2++) {
            const uint32_t bd = sB +
                ((warp_n * 64 + nf2 * 16 + b_r) * 136 + kb + b_c) * 2;
            uint32_t b0, b1, b2, b3;
            LDSM_X4(b0, b1, b2, b3, bd);
#pragma unroll
            for (int mf = 0; mf < 2; mf++) {
                mma_f16(c[mf][nf2 * 2],     a[mf], b0, b1);
                mma_f16(c[mf][nf2 * 2 + 1], a[mf], b2, b3);
            }
        }
    }

    auto put = [&](int row, int col, float v) {
        if (col < 63)                    RW[row * 64 + col] = v;
        else if (col >= 64 && col < 127) RH[row * 64 + col - 64] = v;
    };
#pragma unroll
    for (int mf = 0; mf < 2; mf++) {
        const int row = m0 + warp_m * 32 + mf * 16 + gid;
#pragma unroll
        for (int nf = 0; nf < 8; nf++) {
            const int col = warp_n * 64 + nf * 8 + tig * 2;
            put(row,     col,     c[mf][nf][0]);
            put(row,     col + 1, c[mf][nf][1]);
            put(row + 8, col,     c[mf][nf][2]);
            put(row + 8, col + 1, c[mf][nf][3]);
        }
    }
}

// ===========================================================================
// Flash attention fp16: ldmatrix K/V + direct C->A fragment reuse for P.
// smem (halves): Ks[2][64*136], Vs[2][128*72]; RHs fp32 [128*64].
// ===========================================================================
#define AH_KS   0
#define AH_KST  8704
#define AH_VS   17408
#define AH_VST  9216
#define AH_RHS_BYTES 71680
#define AH_SMEM 104448

__global__ __launch_bounds__(256, 1) void attn_h(
    const __half* __restrict__ Qh, const __half* __restrict__ Kh,
    const __half* __restrict__ Vth, const float* __restrict__ RW,
    const float* __restrict__ RH, __half* __restrict__ AOh)
{
    extern __shared__ char smc[];
    float* RHs = (float*)(smc + AH_RHS_BYTES);
    const uint32_t sb = smem_u32(smc);

    const int tid = threadIdx.x, lane = tid & 31, wm = tid >> 5;
    const int gid = lane >> 2, tig = lane & 3;
    const int m0 = blockIdx.x * 128, h = blockIdx.y, b = blockIdx.z;

    // RH rows -> smem (fp32)
    for (int i4 = tid; i4 < 128 * 16; i4 += 256) {
        int r = i4 >> 4, c4 = i4 & 15;
        *(float4*)&RHs[r * 64 + c4 * 4] =
            *(const float4*)&RH[((b * Lq + m0 + r) * NHd + h) * 64 + c4 * 4];
    }

    // RW bias registers (iter-invariant gather from global)
    const int row0 = wm * 16 + gid;
    float rwv[2][16];
#pragma unroll
    for (int i = 0; i < 2; i++) {
        const int r = row0 + 8 * i;
        const float* RWr = RW + ((b * Lq + m0 + r) * NHd + h) * 64 - (r & 31) + 31;
#pragma unroll
        for (int nf = 0; nf < 8; nf++) {
            rwv[i][nf * 2]     = RWr[((nf * 8 + 2 * tig) & 31)];
            rwv[i][nf * 2 + 1] = RWr[((nf * 8 + 2 * tig + 1) & 31)];
        }
    }
    const int ymr0 = (m0 + row0) >> 5;
    const int ymr1 = (m0 + row0 + 8) >> 5;

    // Q fragments (resident)
    const __half* Qg = Qh + (b * Lq + m0 + wm * 16) * Emb + h * KDim;
    uint32_t qf[8][4];
#pragma unroll
    for (int k16 = 0; k16 < 8; k16++) {
        qf[k16][0] = *(const uint32_t*)(Qg + gid * 512 + k16 * 16 + 2 * tig);
        qf[k16][1] = *(const uint32_t*)(Qg + (gid + 8) * 512 + k16 * 16 + 2 * tig);
        qf[k16][2] = *(const uint32_t*)(Qg + gid * 512 + k16 * 16 + 2 * tig + 8);
        qf[k16][3] = *(const uint32_t*)(Qg + (gid + 8) * 512 + k16 * 16 + 2 * tig + 8);
    }

    float acc[16][4];
#pragma unroll
    for (int n2 = 0; n2 < 16; n2++)
#pragma unroll
        for (int e = 0; e < 4; e++) acc[n2][e] = 0.f;
    float mrow[2] = {-3.0e38f, -3.0e38f};
    float lrow[2] = {0.f, 0.f};

    const __half* Kbase = Kh + (b * Lq) * Emb + h * KDim;
    const __half* Vbase = Vth + (b * NHd + h) * KDim * Lq;

    auto load_tile = [&](int n0, int st) {
#pragma unroll
        for (int it = 0; it < 4; it++) {
            const int idx = it * 256 + tid;
            const int key = idx >> 4, c8 = idx & 15;
            CP_ASYNC16(sb + (AH_KS + st * AH_KST + key * 136 + c8 * 8) * 2,
                       Kbase + (n0 + key) * 512 + c8 * 8);
        }
#pragma unroll
        for (int it = 0; it < 4; it++) {
            const int idx = it * 256 + tid;
            const int d = idx >> 3, c8 = idx & 7;
            CP_ASYNC16(sb + (AH_VS + st * AH_VST + d * 72 + c8 * 8) * 2,
                       Vbase + d * Lq + n0 + c8 * 8);
        }
        CP_COMMIT();
    };

    load_tile(0, 0);

    const int b_r = ((lane >> 4) << 3) + (lane & 7), b_c = ((lane >> 3) & 1) << 3;

    for (int it = 0; it < 16; it++) {
        const int n0 = it * 64;
        const int st = it & 1;
        if (it < 15) { load_tile(n0 + 64, st ^ 1); CP_WAIT1(); }
        else         { CP_WAIT0(); }
        __syncthreads();

        const uint32_t sK = sb + (AH_KS + st * AH_KST) * 2;
        const uint32_t sV = sb + (AH_VS + st * AH_VST) * 2;

        // S = Q K^T
        float s[8][4];
#pragma unroll
        for (int nf = 0; nf < 8; nf++)
#pragma unroll
            for (int e = 0; e < 4; e++) s[nf][e] = 0.f;
#pragma unroll
        for (int k16 = 0; k16 < 8; k16++) {
#pragma unroll
            for (int nf2 = 0; nf2 < 4; nf2++) {
                const uint32_t bd = sK +
                    ((nf2 * 16 + b_r) * 136 + k16 * 16 + b_c) * 2;
                uint32_t b0, b1, b2, b3;
                LDSM_X4(b0, b1, b2, b3, bd);
                mma_f16(s[nf2 * 2],     qf[k16], b0, b1);
                mma_f16(s[nf2 * 2 + 1], qf[k16], b2, b3);
            }
        }

        // bias
        const int seg = n0 >> 5;
        float rh[2][2];
        rh[0][0] = RHs[row0 * 64 + seg - ymr0 + 31];
        rh[0][1] = RHs[row0 * 64 + seg + 1 - ymr0 + 31];
        rh[1][0] = RHs[(row0 + 8) * 64 + seg - ymr1 + 31];
        rh[1][1] = RHs[(row0 + 8) * 64 + seg + 1 - ymr1 + 31];
#pragma unroll
        for (int nf = 0; nf < 8; nf++) {
            const int u = nf >> 2;
            s[nf][0] += rwv[0][nf * 2]     + rh[0][u];
            s[nf][1] += rwv[0][nf * 2 + 1] + rh[0][u];
            s[nf][2] += rwv[1][nf * 2]     + rh[1][u];
            s[nf][3] += rwv[1][nf * 2 + 1] + rh[1][u];
        }

        // online softmax (register resident)
#pragma unroll
        for (int i = 0; i < 2; i++) {
            float mx = s[0][2 * i];
#pragma unroll
            for (int nf = 0; nf < 8; nf++) {
                mx = fmaxf(mx, s[nf][2 * i]);
                mx = fmaxf(mx, s[nf][2 * i + 1]);
            }
            mx = fmaxf(mx, __shfl_xor_sync(0xffffffffu, mx, 1));
            mx = fmaxf(mx, __shfl_xor_sync(0xffffffffu, mx, 2));
            const float mnew = fmaxf(mrow[i], mx);
            const float fsc = fexp2((mrow[i] - mnew) * L2E);
            mrow[i] = mnew;
            float sum = 0.f;
#pragma unroll
            for (int nf = 0; nf < 8; nf++) {
                float p0 = fexp2((s[nf][2 * i] - mnew) * L2E);
                float p1 = fexp2((s[nf][2 * i + 1] - mnew) * L2E);
                sum += p0 + p1;
                s[nf][2 * i] = p0;
                s[nf][2 * i + 1] = p1;
            }
            sum += __shfl_xor_sync(0xffffffffu, sum, 1);
            sum += __shfl_xor_sync(0xffffffffu, sum, 2);
            lrow[i] = lrow[i] * fsc + sum;
#pragma unroll
            for (int n2 = 0; n2 < 16; n2++) {
                acc[n2][2 * i]     *= fsc;
                acc[n2][2 * i + 1] *= fsc;
            }
        }

        // acc += P @ V  (P fragments built directly from S C-fragments)
#pragma unroll
        for (int kk = 0; kk < 4; kk++) {
            uint32_t pa[4];
            pa[0] = packh2(s[2 * kk][0],     s[2 * kk][1]);
            pa[1] = packh2(s[2 * kk][2],     s[2 * kk][3]);
            pa[2] = packh2(s[2 * kk + 1][0], s[2 * kk + 1][1]);
            pa[3] = packh2(s[2 * kk + 1][2], s[2 * kk + 1][3]);
#pragma unroll
            for (int nf2 = 0; nf2 < 8; nf2++) {
                const uint32_t bd = sV +
                    ((nf2 * 16 + b_r) * 72 + kk * 16 + b_c) * 2;
                uint32_t b0, b1, b2, b3;
                LDSM_X4(b0, b1, b2, b3, bd);
                mma_f16(acc[nf2 * 2],     pa, b0, b1);
                mma_f16(acc[nf2 * 2 + 1], pa, b2, b3);
            }
        }
        __syncthreads();
    }

    // epilogue -> AOh fp16
    const float inv0 = 1.f / lrow[0];
    const float inv1 = 1.f / lrow[1];
    const int gm0 = b * Lq + m0 + wm * 16 + gid;
#pragma unroll
    for (int n2 = 0; n2 < 16; n2++) {
        const int col = n2 * 8 + 2 * tig;
        *(__half2*)(AOh + (gm0 * NHd + h) * KDim + col) =
            __floats2half2_rn(acc[n2][0] * inv0, acc[n2][1] * inv0);
        *(__half2*)(AOh + ((gm0 + 8) * NHd + h) * KDim + col) =
            __floats2half2_rn(acc[n2][2] * inv1, acc[n2][3] * inv1);
    }
}

// ---------------------------------------------------------------------------
extern "C" void kernel_launch(void* const* d_in, const int* in_sizes, int n_in,
                              void* d_out, int out_size)
{
    (void)in_sizes; (void)n_in; (void)out_size;
    const float* x  = (const float*)d_in[0];
    const float* Wq = (const float*)d_in[1];
    const float* Wk = (const float*)d_in[2];
    const float* Wv = (const float*)d_in[3];
    const float* Wo = (const float*)d_in[4];
    const float* pw = (const float*)d_in[5];
    const float* ph = (const float*)d_in[6];
    float* out = (float*)d_out;

    __half *xh, *qh, *kh, *vh, *vth, *aoh, *wth, *wtoh, *pth;
    float *rw, *rh;
    cudaGetSymbolAddress((void**)&xh,   g_Xh);
    cudaGetSymbolAddress((void**)&qh,   g_Qh);
    cudaGetSymbolAddress((void**)&kh,   g_Kh);
    cudaGetSymbolAddress((void**)&vh,   g_Vh);
    cudaGetSymbolAddress((void**)&vth,  g_Vth);
    cudaGetSymbolAddress((void**)&aoh,  g_AOh);
    cudaGetSymbolAddress((void**)&wth,  g_Wth);
    cudaGetSymbolAddress((void**)&wtoh, g_WtOh);
    cudaGetSymbolAddress((void**)&pth,  g_Pth);
    cudaGetSymbolAddress((void**)&rw,   g_RW);
    cudaGetSymbolAddress((void**)&rh,   g_RH);

    const float scale = 0.08838834764831845f;  // 1/sqrt(128)

    cudaFuncSetAttribute(gemm_h,
                         cudaFuncAttributeMaxDynamicSharedMemorySize,
                         GH_SMEM_BYTES);
    cudaFuncSetAttribute(relpos_h,
                         cudaFuncAttributeMaxDynamicSharedMemorySize,
                         RP_SMEM_BYTES);
    cudaFuncSetAttribute(attn_h,
                         cudaFuncAttributeMaxDynamicSharedMemorySize,
                         AH_SMEM);

    transpose_w<<<dim3(16, 16, 4), 256>>>(Wq, Wk, Wv, Wo, wth, wtoh);
    build_pt<<<64, 256>>>(pw, ph, pth);
    to_half<<<4096, 256>>>(x, xh);

    gemm_h<<<dim3(12, 64), 256, GH_SMEM_BYTES>>>(
        xh, wth, qh, kh, vh, nullptr, scale);

    vtrans_h<<<dim3(32, 4, 32), 256>>>(vh, vth);

    relpos_h<<<256, 256, RP_SMEM_BYTES>>>(qh, pth, rw, rh);

    attn_h<<<dim3(8, NHd, Bz), 256, AH_SMEM>>>(qh, kh, vth, rw, rh, aoh);

    gemm_h<<<dim3(4, 64), 256, GH_SMEM_BYTES>>>(
        aoh, wtoh, nullptr, nullptr, nullptr, out, 1.0f);
}

// round 9
// speedup vs baseline: 8.4639x; 1.0805x over previous
#include <cuda_runtime.h>
#include <cuda_fp16.h>
#include <cstdint>

// Problem constants
#define Bz    8
#define HHg   32
#define WWg   32
#define Lq    1024          // HHg*WWg
#define Cin   512
#define NHd   4
#define KDim  128
#define Emb   512           // NHd*KDim
#define Mrows 8192          // Bz*Lq

// Scratch (device globals: allocation-free rule)
__device__ __half g_Xh  [Mrows * Cin];
__device__ __half g_Qh  [Mrows * Emb];
__device__ __half g_Kh  [Mrows * Emb];
__device__ __half g_Vh  [Mrows * Emb];
__device__ __half g_AOh [Mrows * Emb];
__device__ float  g_RW  [Mrows * NHd * 64];      // 63 used, padded
__device__ float  g_RH  [Mrows * NHd * 64];
__device__ __half g_Wth [3 * Emb * Cin];         // transposed Wq|Wk|Wv [1536][512]
__device__ __half g_WtOh[Emb * Emb];             // transposed Wo [512][512]
__device__ __half g_Pth [128 * 128];             // padded pos tables [r][d]

// ===========================================================================
// Helpers
// ===========================================================================
__device__ __forceinline__ uint32_t smem_u32(const void* p) {
    uint32_t a;
    asm("{ .reg .u64 t; cvta.to.shared.u64 t, %1; cvt.u32.u64 %0, t; }"
        : "=r"(a) : "l"(p));
    return a;
}
#define CP_ASYNC16(dst, src) \
    asm volatile("cp.async.cg.shared.global [%0], [%1], 16;" \
                 :: "r"(dst), "l"(src) : "memory")
#define CP_COMMIT() asm volatile("cp.async.commit_group;" ::: "memory")
#define CP_WAIT1()  asm volatile("cp.async.wait_group 1;" ::: "memory")
#define CP_WAIT0()  asm volatile("cp.async.wait_group 0;" ::: "memory")

#define LDSM_X4(r0, r1, r2, r3, addr) \
    asm volatile("ldmatrix.sync.aligned.m8n8.x4.shared.b16 {%0,%1,%2,%3}, [%4];" \
        : "=r"(r0), "=r"(r1), "=r"(r2), "=r"(r3) : "r"(addr))
#define LDSM_X4_T(r0, r1, r2, r3, addr) \
    asm volatile("ldmatrix.sync.aligned.m8n8.x4.trans.shared.b16 {%0,%1,%2,%3}, [%4];" \
        : "=r"(r0), "=r"(r1), "=r"(r2), "=r"(r3) : "r"(addr))

__device__ __forceinline__ void mma_f16(float* c, const uint32_t* a,
                                        uint32_t b0, uint32_t b1) {
    asm volatile(
        "mma.sync.aligned.m16n8k16.row.col.f32.f16.f16.f32 "
        "{%0,%1,%2,%3}, {%4,%5,%6,%7}, {%8,%9}, {%0,%1,%2,%3};"
        : "+f"(c[0]), "+f"(c[1]), "+f"(c[2]), "+f"(c[3])
        : "r"(a[0]), "r"(a[1]), "r"(a[2]), "r"(a[3]), "r"(b0), "r"(b1));
}
__device__ __forceinline__ uint32_t packh2(float a, float b) {
    __half2 h = __floats2half2_rn(a, b);
    return *(uint32_t*)&h;
}

// Fast exp2 on the FMA pipe
__device__ __forceinline__ float fexp2(float x) {
    x = fmaxf(x, -120.f);
    float r = rintf(x);
    float f = x - r;
    float p =              0.0013333558f;
    p = fmaf(p, f, 0.0096181291f);
    p = fmaf(p, f, 0.0555041087f);
    p = fmaf(p, f, 0.2402265069f);
    p = fmaf(p, f, 0.6931471806f);
    p = fmaf(p, f, 1.0f);
    int e = (int)r;
    return p * __int_as_float((e + 127) << 23);
}
#define L2E 1.4426950408889634f

// ===========================================================================
// Fused prep: z<4 -> weight transpose; z==4 -> build Pt; z>=5 -> x->fp16.
// grid (16,16,21), 256 threads.
// ===========================================================================
__global__ __launch_bounds__(256) void prep_kernel(
    const float* __restrict__ x,
    const float* __restrict__ Wq, const float* __restrict__ Wk,
    const float* __restrict__ Wv, const float* __restrict__ Wo,
    const float* __restrict__ pw, const float* __restrict__ ph,
    __half* __restrict__ xh, __half* __restrict__ Wt,
    __half* __restrict__ WtO, __half* __restrict__ Pt)
{
    const int z = blockIdx.z;
    const int tid = threadIdx.x;
    if (z < 4) {
        __shared__ float t[32][33];
        const float* W = (z == 0) ? Wq : (z == 1) ? Wk : (z == 2) ? Wv : Wo;
        __half* O = (z == 3) ? WtO : (Wt + z * Emb * Cin);
        const int tx = tid & 31, ty = tid >> 5;
        const int k0 = blockIdx.y * 32, n0 = blockIdx.x * 32;
#pragma unroll
        for (int i = 0; i < 4; i++)
            t[ty + i * 8][tx] = W[(k0 + ty + i * 8) * 512 + n0 + tx];
        __syncthreads();
#pragma unroll
        for (int i = 0; i < 4; i++)
            O[(n0 + ty + i * 8) * 512 + k0 + tx] = __float2half(t[tx][ty + i * 8]);
    } else if (z == 4) {
        const int id = blockIdx.y * 16 + blockIdx.x;
        if (id < 64) {
            const int idx = id * 256 + tid;          // 0..16383
            const int r = idx >> 7, d = idx & 127;
            float v = 0.f;
            if (r < 63)                  v = pw[d * 63 + r];
            else if (r >= 64 && r < 127) v = ph[d * 63 + (r - 64)];
            Pt[idx] = __float2half(v);
        }
    } else {
        const int id = (z - 5) * 256 + blockIdx.y * 16 + blockIdx.x;  // 0..4095
        const int i = (id * 256 + tid) * 4;
        float4 v = *(const float4*)&x[i];
        *(__half2*)&xh[i]     = __floats2half2_rn(v.x, v.y);
        *(__half2*)&xh[i + 2] = __floats2half2_rn(v.z, v.w);
    }
}

// ===========================================================================
// fp16 mma GEMM: C = alpha * A[M,512] @ Bt[N,512]^T
// CTA 128x128, 8 warps (32x64), K-chunk 64, 3-stage cp.async, 1 sync/iter.
// ===========================================================================
#define GH_A_HALVES (128 * 72)
#define GH_STAGE_HALVES (2 * GH_A_HALVES)
#define GH_SMEM_BYTES (3 * GH_STAGE_HALVES * 2)   // 110592

__global__ __launch_bounds__(256, 2) void gemm_h(
    const __half* __restrict__ A, const __half* __restrict__ Bt,
    __half* __restrict__ C0, __half* __restrict__ C1, __half* __restrict__ C2,
    float* __restrict__ Cf, float alpha0)
{
    extern __shared__ __half smh[];
    const uint32_t sb = smem_u32(smh);
    const int tid = threadIdx.x, lane = tid & 31, wid = tid >> 5;
    const int warp_m = wid & 3, warp_n = wid >> 2;
    const int gid = lane >> 2, tig = lane & 3;

    const int bx = blockIdx.x, outi = bx >> 2;
    __half* Ch = (outi == 0) ? C0 : (outi == 1) ? C1 : C2;
    const float alpha = (outi == 0) ? alpha0 : 1.0f;
    const int m0 = blockIdx.y * 128;
    const int nrow0 = bx * 128;
    const int ncol0 = (bx & 3) * 128;

    const __half* Ab = A + m0 * 512;
    const __half* Bb = Bt + nrow0 * 512;

    float c[2][8][4];
#pragma unroll
    for (int mf = 0; mf < 2; mf++)
#pragma unroll
        for (int nf = 0; nf < 8; nf++)
#pragma unroll
            for (int e = 0; e < 4; e++) c[mf][nf][e] = 0.f;

    auto issue = [&](int kc, int s) {
#pragma unroll
        for (int it = 0; it < 4; it++) {
            const int idx = it * 256 + tid;
            const int row = idx >> 3, c8 = idx & 7;
            const uint32_t dA = sb + (s * GH_STAGE_HALVES + row * 72 + c8 * 8) * 2;
            CP_ASYNC16(dA, Ab + row * 512 + kc * 64 + c8 * 8);
            CP_ASYNC16(dA + GH_A_HALVES * 2, Bb + row * 512 + kc * 64 + c8 * 8);
        }
        CP_COMMIT();
    };

    issue(0, 0);
    issue(1, 1);

    const int a_r = lane & 15, a_c = (lane >> 4) << 3;
    const int b_r = ((lane >> 4) << 3) + (lane & 7), b_c = ((lane >> 3) & 1) << 3;

    for (int kc = 0; kc < 8; kc++) {
        if (kc == 7) { CP_WAIT0(); } else { CP_WAIT1(); }
        __syncthreads();

        const uint32_t sA = sb + (kc % 3) * GH_STAGE_HALVES * 2;
        const uint32_t sB = sA + GH_A_HALVES * 2;

#pragma unroll
        for (int t = 0; t < 4; t++) {
            const int kb = t * 16;
            uint32_t a[2][4];
#pragma unroll
            for (int mf = 0; mf < 2; mf++) {
                const uint32_t ad = sA +
                    ((warp_m * 32 + mf * 16 + a_r) * 72 + kb + a_c) * 2;
                LDSM_X4(a[mf][0], a[mf][1], a[mf][2], a[mf][3], ad);
            }
#pragma unroll
            for (int nf2 = 0; nf2 < 4; nf2++) {
                const uint32_t bd = sB +
                    ((warp_n * 64 + nf2 * 16 + b_r) * 72 + kb + b_c) * 2;
                uint32_t b0, b1, b2, b3;
                LDSM_X4(b0, b1, b2, b3, bd);
#pragma unroll
                for (int mf = 0; mf < 2; mf++) {
                    mma_f16(c[mf][nf2 * 2],     a[mf], b0, b1);
                    mma_f16(c[mf][nf2 * 2 + 1], a[mf], b2, b3);
                }
            }
        }
        if (kc < 6) issue(kc + 2, (kc + 2) % 3);
    }

#pragma unroll
    for (int mf = 0; mf < 2; mf++) {
        const int row = m0 + warp_m * 32 + mf * 16 + gid;
#pragma unroll
        for (int nf = 0; nf < 8; nf++) {
            const int col = ncol0 + warp_n * 64 + nf * 8 + tig * 2;
            float v0 = c[mf][nf][0] * alpha, v1 = c[mf][nf][1] * alpha;
            float v2 = c[mf][nf][2] * alpha, v3 = c[mf][nf][3] * alpha;
            if (Cf) {
                *(float2*)(Cf + row * 512 + col)       = make_float2(v0, v1);
                *(float2*)(Cf + (row + 8) * 512 + col) = make_float2(v2, v3);
            } else {
                *(__half2*)(Ch + row * 512 + col)       = __floats2half2_rn(v0, v1);
                *(__half2*)(Ch + (row + 8) * 512 + col) = __floats2half2_rn(v2, v3);
            }
        }
    }
}

// ===========================================================================
// relpos fp16 mma: Qflat[32768,128] @ Pt[128,128]^T -> RW|RH fp32
// ===========================================================================
#define RP_A_HALVES (128 * 136)
#define RP_SMEM_BYTES (2 * RP_A_HALVES * 2)     // 69632

__global__ __launch_bounds__(256) void relpos_h(
    const __half* __restrict__ Q, const __half* __restrict__ Pt,
    float* __restrict__ RW, float* __restrict__ RH)
{
    extern __shared__ __half smh[];
    const uint32_t sb = smem_u32(smh);
    const int tid = threadIdx.x, lane = tid & 31, wid = tid >> 5;
    const int warp_m = wid & 3, warp_n = wid >> 2;
    const int gid = lane >> 2, tig = lane & 3;
    const int m0 = blockIdx.x * 128;

#pragma unroll
    for (int it = 0; it < 8; it++) {
        const int idx = it * 256 + tid;
        const int row = idx >> 4, c8 = idx & 15;
        CP_ASYNC16(sb + (row * 136 + c8 * 8) * 2,
                   Q + (m0 + row) * 128 + c8 * 8);
        CP_ASYNC16(sb + (RP_A_HALVES + row * 136 + c8 * 8) * 2,
                   Pt + row * 128 + c8 * 8);
    }
    CP_COMMIT();
    CP_WAIT0();
    __syncthreads();

    float c[2][8][4];
#pragma unroll
    for (int mf = 0; mf < 2; mf++)
#pragma unroll
        for (int nf = 0; nf < 8; nf++)
#pragma unroll
            for (int e = 0; e < 4; e++) c[mf][nf][e] = 0.f;

    const int a_r = lane & 15, a_c = (lane >> 4) << 3;
    const int b_r = ((lane >> 4) << 3) + (lane & 7), b_c = ((lane >> 3) & 1) << 3;
    const uint32_t sB = sb + RP_A_HALVES * 2;

#pragma unroll
    for (int t = 0; t < 8; t++) {
        const int kb = t * 16;
        uint32_t a[2][4];
#pragma unroll
        for (int mf = 0; mf < 2; mf++) {
            const uint32_t ad = sb +
                ((warp_m * 32 + mf * 16 + a_r) * 136 + kb + a_c) * 2;
            LDSM_X4(a[mf][0], a[mf][1], a[mf][2], a[mf][3], ad);
        }
#pragma unroll
        for (int nf2 = 0; nf2 < 4; nf2++) {
            const uint32_t bd = sB +
                ((warp_n * 64 + nf2 * 16 + b_r) * 136 + kb + b_c) * 2;
            uint32_t b0, b1, b2, b3;
            LDSM_X4(b0, b1, b2, b3, bd);
#pragma unroll
            for (int mf = 0; mf < 2; mf++) {
                mma_f16(c[mf][nf2 * 2],     a[mf], b0, b1);
                mma_f16(c[mf][nf2 * 2 + 1], a[mf], b2, b3);
            }
        }
    }

    auto put = [&](int row, int col, float v) {
        if (col < 63)                    RW[row * 64 + col] = v;
        else if (col >= 64 && col < 127) RH[row * 64 + col - 64] = v;
    };
#pragma unroll
    for (int mf = 0; mf < 2; mf++) {
        const int row = m0 + warp_m * 32 + mf * 16 + gid;
#pragma unroll
        for (int nf = 0; nf < 8; nf++) {
            const int col = warp_n * 64 + nf * 8 + tig * 2;
            put(row,     col,     c[mf][nf][0]);
            put(row,     col + 1, c[mf][nf][1]);
            put(row + 8, col,     c[mf][nf][2]);
            put(row + 8, col + 1, c[mf][nf][3]);
        }
    }
}

// ===========================================================================
// Flash attention fp16: V loaded via ldmatrix.trans from [key][d] tiles
// (no pre-transpose), 3-stage pipeline, 1 sync/iter.
// smem: 3 stages x (K[64][136] + V[64][136]) halves + RHs fp32 [128][64].
// ===========================================================================
#define AH_STAGE_HALVES (2 * 64 * 136)            // K + V per stage: 17408
#define AH_K_OFF 0
#define AH_V_OFF (64 * 136)
#define AH_RHS_BYTES (3 * AH_STAGE_HALVES * 2)    // 104448
#define AH_SMEM (AH_RHS_BYTES + 128 * 64 * 4)     // 137216

__global__ __launch_bounds__(256, 1) void attn_h(
    const __half* __restrict__ Qh, const __half* __restrict__ Kh,
    const __half* __restrict__ Vh, const float* __restrict__ RW,
    const float* __restrict__ RH, __half* __restrict__ AOh)
{
    extern __shared__ char smc[];
    float* RHs = (float*)(smc + AH_RHS_BYTES);
    const uint32_t sb = smem_u32(smc);

    const int tid = threadIdx.x, lane = tid & 31, wm = tid >> 5;
    const int gid = lane >> 2, tig = lane & 3;
    const int m0 = blockIdx.x * 128, h = blockIdx.y, b = blockIdx.z;

    const __half* Kbase = Kh + (b * Lq) * Emb + h * KDim;
    const __half* Vbase = Vh + (b * Lq) * Emb + h * KDim;

    auto load_tile = [&](int n0, int st) {
#pragma unroll
        for (int it = 0; it < 4; it++) {
            const int idx = it * 256 + tid;
            const int key = idx >> 4, c8 = idx & 15;
            const uint32_t d0 = sb + (st * AH_STAGE_HALVES + key * 136 + c8 * 8) * 2;
            CP_ASYNC16(d0, Kbase + (n0 + key) * 512 + c8 * 8);
            CP_ASYNC16(d0 + AH_V_OFF * 2, Vbase + (n0 + key) * 512 + c8 * 8);
        }
        CP_COMMIT();
    };

    load_tile(0, 0);
    load_tile(64, 1);

    // RH rows -> smem (fp32)
    for (int i4 = tid; i4 < 128 * 16; i4 += 256) {
        int r = i4 >> 4, c4 = i4 & 15;
        *(float4*)&RHs[r * 64 + c4 * 4] =
            *(const float4*)&RH[((b * Lq + m0 + r) * NHd + h) * 64 + c4 * 4];
    }

    // RW bias registers (iter-invariant gather from global)
    const int row0 = wm * 16 + gid;
    float rwv[2][16];
#pragma unroll
    for (int i = 0; i < 2; i++) {
        const int r = row0 + 8 * i;
        const float* RWr = RW + ((b * Lq + m0 + r) * NHd + h) * 64 - (r & 31) + 31;
#pragma unroll
        for (int nf = 0; nf < 8; nf++) {
            rwv[i][nf * 2]     = RWr[((nf * 8 + 2 * tig) & 31)];
            rwv[i][nf * 2 + 1] = RWr[((nf * 8 + 2 * tig + 1) & 31)];
        }
    }
    const int ymr0 = (m0 + row0) >> 5;
    const int ymr1 = (m0 + row0 + 8) >> 5;

    // Q fragments (resident)
    const __half* Qg = Qh + (b * Lq + m0 + wm * 16) * Emb + h * KDim;
    uint32_t qf[8][4];
#pragma unroll
    for (int k16 = 0; k16 < 8; k16++) {
        qf[k16][0] = *(const uint32_t*)(Qg + gid * 512 + k16 * 16 + 2 * tig);
        qf[k16][1] = *(const uint32_t*)(Qg + (gid + 8) * 512 + k16 * 16 + 2 * tig);
        qf[k16][2] = *(const uint32_t*)(Qg + gid * 512 + k16 * 16 + 2 * tig + 8);
        qf[k16][3] = *(const uint32_t*)(Qg + (gid + 8) * 512 + k16 * 16 + 2 * tig + 8);
    }

    float acc[16][4];
#pragma unroll
    for (int n2 = 0; n2 < 16; n2++)
#pragma unroll
        for (int e = 0; e < 4; e++) acc[n2][e] = 0.f;
    float mrow[2] = {-3.0e38f, -3.0e38f};
    float lrow[2] = {0.f, 0.f};

    const int b_r = ((lane >> 4) << 3) + (lane & 7), b_c = ((lane >> 3) & 1) << 3;
    const int vt_r = lane & 15, vt_c = (lane >> 4) << 3;   // trans-ldsm lane map

    for (int it = 0; it < 16; it++) {
        const int n0 = it * 64;
        if (it == 15) { CP_WAIT0(); } else { CP_WAIT1(); }
        __syncthreads();

        const uint32_t sK = sb + ((it % 3) * AH_STAGE_HALVES) * 2;
        const uint32_t sV = sK + AH_V_OFF * 2;

        // S = Q K^T
        float s[8][4];
#pragma unroll
        for (int nf = 0; nf < 8; nf++)
#pragma unroll
            for (int e = 0; e < 4; e++) s[nf][e] = 0.f;
#pragma unroll
        for (int k16 = 0; k16 < 8; k16++) {
#pragma unroll
            for (int nf2 = 0; nf2 < 4; nf2++) {
                const uint32_t bd = sK +
                    ((nf2 * 16 + b_r) * 136 + k16 * 16 + b_c) * 2;
                uint32_t b0, b1, b2, b3;
                LDSM_X4(b0, b1, b2, b3, bd);
                mma_f16(s[nf2 * 2],     qf[k16], b0, b1);
                mma_f16(s[nf2 * 2 + 1], qf[k16], b2, b3);
            }
        }

        // bias
        const int seg = n0 >> 5;
        float rh[2][2];
        rh[0][0] = RHs[row0 * 64 + seg - ymr0 + 31];
        rh[0][1] = RHs[row0 * 64 + seg + 1 - ymr0 + 31];
        rh[1][0] = RHs[(row0 + 8) * 64 + seg - ymr1 + 31];
        rh[1][1] = RHs[(row0 + 8) * 64 + seg + 1 - ymr1 + 31];
#pragma unroll
        for (int nf = 0; nf < 8; nf++) {
            const int u = nf >> 2;
            s[nf][0] += rwv[0][nf * 2]     + rh[0][u];
            s[nf][1] += rwv[0][nf * 2 + 1] + rh[0][u];
            s[nf][2] += rwv[1][nf * 2]     + rh[1][u];
            s[nf][3] += rwv[1][nf * 2 + 1] + rh[1][u];
        }

        // online softmax (register resident)
#pragma unroll
        for (int i = 0; i < 2; i++) {
            float mx = s[0][2 * i];
#pragma unroll
            for (int nf = 0; nf < 8; nf++) {
                mx = fmaxf(mx, s[nf][2 * i]);
                mx = fmaxf(mx, s[nf][2 * i + 1]);
            }
            mx = fmaxf(mx, __shfl_xor_sync(0xffffffffu, mx, 1));
            mx = fmaxf(mx, __shfl_xor_sync(0xffffffffu, mx, 2));
            const float mnew = fmaxf(mrow[i], mx);
            const float fsc = fexp2((mrow[i] - mnew) * L2E);
            mrow[i] = mnew;
            float sum = 0.f;
#pragma unroll
            for (int nf = 0; nf < 8; nf++) {
                float p0 = fexp2((s[nf][2 * i] - mnew) * L2E);
                float p1 = fexp2((s[nf][2 * i + 1] - mnew) * L2E);
                sum += p0 + p1;
                s[nf][2 * i] = p0;
                s[nf][2 * i + 1] = p1;
            }
            sum += __shfl_xor_sync(0xffffffffu, sum, 1);
            sum += __shfl_xor_sync(0xffffffffu, sum, 2);
            lrow[i] = lrow[i] * fsc + sum;
#pragma unroll
            for (int n2 = 0; n2 < 16; n2++) {
                acc[n2][2 * i]     *= fsc;
                acc[n2][2 * i + 1] *= fsc;
            }
        }

        // acc += P @ V  (P from S C-fragments; V via ldmatrix.trans on [key][d])
#pragma unroll
        for (int kk = 0; kk < 4; kk++) {
            uint32_t pa[4];
            pa[0] = packh2(s[2 * kk][0],     s[2 * kk][1]);
            pa[1] = packh2(s[2 * kk][2],     s[2 * kk][3]);
            pa[2] = packh2(s[2 * kk + 1][0], s[2 * kk + 1][1]);
            pa[3] = packh2(s[2 * kk + 1][2], s[2 * kk + 1][3]);
#pragma unroll
            for (int nf2 = 0; nf2 < 8; nf2++) {
                const uint32_t bd = sV +
                    ((kk * 16 + vt_r) * 136 + nf2 * 16 + vt_c) * 2;
                uint32_t b0, b1, b2, b3;
                LDSM_X4_T(b0, b1, b2, b3, bd);
                mma_f16(acc[nf2 * 2],     pa, b0, b1);
                mma_f16(acc[nf2 * 2 + 1], pa, b2, b3);
            }
        }

        if (it < 14) load_tile(n0 + 128, (it + 2) % 3);
    }

    // epilogue -> AOh fp16
    const float inv0 = 1.f / lrow[0];
    const float inv1 = 1.f / lrow[1];
    const int gm0 = b * Lq + m0 + wm * 16 + gid;
#pragma unroll
    for (int n2 = 0; n2 < 16; n2++) {
        const int col = n2 * 8 + 2 * tig;
        *(__half2*)(AOh + (gm0 * NHd + h) * KDim + col) =
            __floats2half2_rn(acc[n2][0] * inv0, acc[n2][1] * inv0);
        *(__half2*)(AOh + ((gm0 + 8) * NHd + h) * KDim + col) =
            __floats2half2_rn(acc[n2][2] * inv1, acc[n2][3] * inv1);
    }
}

// ---------------------------------------------------------------------------
extern "C" void kernel_launch(void* const* d_in, const int* in_sizes, int n_in,
                              void* d_out, int out_size)
{
    (void)in_sizes; (void)n_in; (void)out_size;
    const float* x  = (const float*)d_in[0];
    const float* Wq = (const float*)d_in[1];
    const float* Wk = (const float*)d_in[2];
    const float* Wv = (const float*)d_in[3];
    const float* Wo = (const float*)d_in[4];
    const float* pw = (const float*)d_in[5];
    const float* ph = (const float*)d_in[6];
    float* out = (float*)d_out;

    __half *xh, *qh, *kh, *vh, *aoh, *wth, *wtoh, *pth;
    float *rw, *rh;
    cudaGetSymbolAddress((void**)&xh,   g_Xh);
    cudaGetSymbolAddress((void**)&qh,   g_Qh);
    cudaGetSymbolAddress((void**)&kh,   g_Kh);
    cudaGetSymbolAddress((void**)&vh,   g_Vh);
    cudaGetSymbolAddress((void**)&aoh,  g_AOh);
    cudaGetSymbolAddress((void**)&wth,  g_Wth);
    cudaGetSymbolAddress((void**)&wtoh, g_WtOh);
    cudaGetSymbolAddress((void**)&pth,  g_Pth);
    cudaGetSymbolAddress((void**)&rw,   g_RW);
    cudaGetSymbolAddress((void**)&rh,   g_RH);

    const float scale = 0.08838834764831845f;  // 1/sqrt(128)

    cudaFuncSetAttribute(gemm_h,
                         cudaFuncAttributeMaxDynamicSharedMemorySize,
                         GH_SMEM_BYTES);
    cudaFuncSetAttribute(relpos_h,
                         cudaFuncAttributeMaxDynamicSharedMemorySize,
                         RP_SMEM_BYTES);
    cudaFuncSetAttribute(attn_h,
                         cudaFuncAttributeMaxDynamicSharedMemorySize,
                         AH_SMEM);

    prep_kernel<<<dim3(16, 16, 21), 256>>>(
        x, Wq, Wk, Wv, Wo, pw, ph, xh, wth, wtoh, pth);

    gemm_h<<<dim3(12, 64), 256, GH_SMEM_BYTES>>>(
        xh, wth, qh, kh, vh, nullptr, scale);

    relpos_h<<<256, 256, RP_SMEM_BYTES>>>(qh, pth, rw, rh);

    attn_h<<<dim3(8, NHd, Bz), 256, AH_SMEM>>>(qh, kh, vh, rw, rh, aoh);

    gemm_h<<<dim3(4, 64), 256, GH_SMEM_BYTES>>>(
        aoh, wtoh, nullptr, nullptr, nullptr, out, 1.0f);
}